// round 1
// baseline (speedup 1.0000x reference)
#include <cuda_runtime.h>
#include <cstdint>

#define N_NODES 50000
#define N_EDGES 800000
#define N_GRAPHS 256
#define IN_CH 128
#define HID 256

// ---------------- scratch (device globals; no allocation allowed) -------------
__device__ float g_deg[N_NODES];
__device__ float g_dis[N_NODES];
__device__ float g_ew[N_EDGES];
__device__ float g_xw[(size_t)N_NODES * HID];
__device__ float g_hA[(size_t)N_NODES * HID];
__device__ float g_hB[(size_t)N_NODES * HID];
__device__ float g_pooled[N_GRAPHS * HID];
__device__ float g_counts[N_GRAPHS];

// ---------------- helpers ----------------------------------------------------
__device__ __forceinline__ void red_add_v4(float* addr, float4 v) {
    asm volatile("red.global.add.v4.f32 [%0], {%1,%2,%3,%4};"
                 :: "l"(addr), "f"(v.x), "f"(v.y), "f"(v.z), "f"(v.w)
                 : "memory");
}

// ---------------- init: deg=1 (self loop), pooled=0, counts=0 ----------------
__global__ void k_init(float* deg, float* pooled, float* counts) {
    int i = blockIdx.x * blockDim.x + threadIdx.x;
    if (i < N_NODES) deg[i] = 1.0f;
    if (i < N_GRAPHS * HID) pooled[i] = 0.0f;
    if (i < N_GRAPHS) counts[i] = 0.0f;
}

// ---------------- degree count (col = edge_index[1]) -------------------------
__global__ void k_count_deg(const int* __restrict__ col, float* __restrict__ deg) {
    int e = blockIdx.x * blockDim.x + threadIdx.x;
    if (e < N_EDGES) atomicAdd(&deg[col[e]], 1.0f);
}

__global__ void k_dis(const float* __restrict__ deg, float* __restrict__ dis) {
    int i = blockIdx.x * blockDim.x + threadIdx.x;
    if (i < N_NODES) dis[i] = rsqrtf(deg[i]);   // deg >= 1 always (self loop)
}

__global__ void k_edge_w(const int* __restrict__ row, const int* __restrict__ col,
                         const float* __restrict__ dis, float* __restrict__ ew) {
    int e = blockIdx.x * blockDim.x + threadIdx.x;
    if (e < N_EDGES) ew[e] = dis[row[e]] * dis[col[e]];
}

// ---------------- SGEMM: C[M,256] = op(A)[M,K] @ B[K,256] --------------------
// BM=128, BN=64, BK=16, 256 threads, thread tile 8x4.
template <bool RELU_A>
__global__ __launch_bounds__(256) void k_sgemm(const float* __restrict__ A,
                                               const float* __restrict__ B,
                                               float* __restrict__ C,
                                               int M, int K) {
    __shared__ float As[16][128];
    __shared__ float Bs[16][64];
    const int bm = blockIdx.y * 128;
    const int bn = blockIdx.x * 64;
    const int tid = threadIdx.x;
    const int tx = tid % 16;   // n direction (x4)
    const int ty = tid / 16;   // m direction (x8)

    float acc[8][4];
#pragma unroll
    for (int i = 0; i < 8; i++)
#pragma unroll
        for (int j = 0; j < 4; j++) acc[i][j] = 0.0f;

    for (int k0 = 0; k0 < K; k0 += 16) {
        // load A tile: 128x16 -> 512 float4, 2 per thread
#pragma unroll
        for (int l = 0; l < 2; l++) {
            int idx = tid + l * 256;         // 0..511
            int m   = idx >> 2;              // 0..127
            int kk  = (idx & 3) * 4;         // 0,4,8,12
            int gm  = bm + m;
            float4 v = make_float4(0.f, 0.f, 0.f, 0.f);
            if (gm < M) v = *(const float4*)&A[(size_t)gm * K + k0 + kk];
            if (RELU_A) {
                v.x = fmaxf(v.x, 0.f); v.y = fmaxf(v.y, 0.f);
                v.z = fmaxf(v.z, 0.f); v.w = fmaxf(v.w, 0.f);
            }
            As[kk + 0][m] = v.x; As[kk + 1][m] = v.y;
            As[kk + 2][m] = v.z; As[kk + 3][m] = v.w;
        }
        // load B tile: 16x64 -> 256 float4, 1 per thread
        {
            int kk = tid >> 4;               // 0..15
            int n  = (tid & 15) * 4;         // 0..60
            float4 v = *(const float4*)&B[(size_t)(k0 + kk) * HID + bn + n];
            Bs[kk][n + 0] = v.x; Bs[kk][n + 1] = v.y;
            Bs[kk][n + 2] = v.z; Bs[kk][n + 3] = v.w;
        }
        __syncthreads();
#pragma unroll
        for (int k = 0; k < 16; k++) {
            float a[8], b[4];
#pragma unroll
            for (int i = 0; i < 8; i++) a[i] = As[k][ty * 8 + i];
#pragma unroll
            for (int j = 0; j < 4; j++) b[j] = Bs[k][tx * 4 + j];
#pragma unroll
            for (int i = 0; i < 8; i++)
#pragma unroll
                for (int j = 0; j < 4; j++) acc[i][j] = fmaf(a[i], b[j], acc[i][j]);
        }
        __syncthreads();
    }
#pragma unroll
    for (int i = 0; i < 8; i++) {
        int gm = bm + ty * 8 + i;
        if (gm < M) {
            float4 v = make_float4(acc[i][0], acc[i][1], acc[i][2], acc[i][3]);
            *(float4*)&C[(size_t)gm * HID + bn + tx * 4] = v;
        }
    }
}

// ---------------- out = xw * dis^2 + b (self-loop + bias, also zeros dests) --
__global__ void k_init_out(const float* __restrict__ xw, const float* __restrict__ dis,
                           const float* __restrict__ b, float* __restrict__ out) {
    size_t idx = (size_t)blockIdx.x * blockDim.x + threadIdx.x;
    if (idx >= (size_t)N_NODES * HID) return;
    int i  = (int)(idx >> 8);     // /256
    int ch = (int)(idx & 255);
    float d = dis[i];
    out[idx] = xw[idx] * d * d + b[ch];
}

// ---------------- edge scatter: out[col] += xw[row] * ew ---------------------
// 64 threads per edge (one float4 each covering 256 ch), 4 edges per block.
__global__ __launch_bounds__(256) void k_scatter(const float* __restrict__ xw,
                                                 const int* __restrict__ row,
                                                 const int* __restrict__ col,
                                                 const float* __restrict__ ew,
                                                 float* __restrict__ out) {
    int gid  = blockIdx.x * 4 + (threadIdx.x >> 6);
    int lane = threadIdx.x & 63;
    if (gid >= N_EDGES) return;
    int r = row[gid];
    int c = col[gid];
    float w = ew[gid];
    float4 v = *(const float4*)&xw[(size_t)r * HID + lane * 4];
    v.x *= w; v.y *= w; v.z *= w; v.w *= w;
    red_add_v4(&out[(size_t)c * HID + lane * 4], v);
}

// ---------------- graph counts -----------------------------------------------
__global__ void k_counts(const int* __restrict__ batch, float* __restrict__ counts) {
    int i = blockIdx.x * blockDim.x + threadIdx.x;
    if (i < N_NODES) atomicAdd(&counts[batch[i]], 1.0f);
}

// ---------------- pool: pooled[batch[i]] += relu(h[i]) -----------------------
__global__ __launch_bounds__(256) void k_pool(const float* __restrict__ h,
                                              const int* __restrict__ batch,
                                              float* __restrict__ pooled) {
    int nid  = blockIdx.x * 4 + (threadIdx.x >> 6);
    int lane = threadIdx.x & 63;
    if (nid >= N_NODES) return;
    int b = batch[nid];
    float4 v = *(const float4*)&h[(size_t)nid * HID + lane * 4];
    v.x = fmaxf(v.x, 0.f); v.y = fmaxf(v.y, 0.f);
    v.z = fmaxf(v.z, 0.f); v.w = fmaxf(v.w, 0.f);
    red_add_v4(&pooled[(size_t)b * HID + lane * 4], v);
}

// ---------------- FFN: out[g] = relu(pooled/cnt @ Wf + bf) @ Wo + bo ---------
__global__ __launch_bounds__(256) void k_ffn(const float* __restrict__ pooled,
                                             const float* __restrict__ counts,
                                             const float* __restrict__ Wf,
                                             const float* __restrict__ bf,
                                             const float* __restrict__ Wo,
                                             const float* __restrict__ bo,
                                             float* __restrict__ out) {
    int g = blockIdx.x;
    int t = threadIdx.x;
    __shared__ float prow[HID];
    __shared__ float red[HID];
    float inv = 1.0f / fmaxf(counts[g], 1.0f);
    prow[t] = pooled[g * HID + t] * inv;
    __syncthreads();
    float acc = bf[t];
#pragma unroll 8
    for (int k = 0; k < HID; k++) acc = fmaf(prow[k], Wf[k * HID + t], acc);
    red[t] = fmaxf(acc, 0.0f) * Wo[t];
    __syncthreads();
    for (int s = 128; s > 0; s >>= 1) {
        if (t < s) red[t] += red[t + s];
        __syncthreads();
    }
    if (t == 0) out[g] = red[0] + bo[0];
}

// ---------------- host side ---------------------------------------------------
extern "C" void kernel_launch(void* const* d_in, const int* in_sizes, int n_in,
                              void* d_out, int out_size) {
    const float* x    = (const float*)d_in[0];
    const int*   ei   = (const int*)d_in[1];
    const int*   batch= (const int*)d_in[2];
    const float* W1   = (const float*)d_in[3];
    const float* b1   = (const float*)d_in[4];
    const float* W2   = (const float*)d_in[5];
    const float* b2   = (const float*)d_in[6];
    const float* W3   = (const float*)d_in[7];
    const float* b3   = (const float*)d_in[8];
    const float* Wf   = (const float*)d_in[9];
    const float* bf   = (const float*)d_in[10];
    const float* Wo   = (const float*)d_in[11];
    const float* bo   = (const float*)d_in[12];
    float* out = (float*)d_out;

    const int* row = ei;             // edge_index[0]
    const int* col = ei + N_EDGES;   // edge_index[1]

    float *deg, *dis, *ew, *xw, *hA, *hB, *pooled, *counts;
    cudaGetSymbolAddress((void**)&deg,    g_deg);
    cudaGetSymbolAddress((void**)&dis,    g_dis);
    cudaGetSymbolAddress((void**)&ew,     g_ew);
    cudaGetSymbolAddress((void**)&xw,     g_xw);
    cudaGetSymbolAddress((void**)&hA,     g_hA);
    cudaGetSymbolAddress((void**)&hB,     g_hB);
    cudaGetSymbolAddress((void**)&pooled, g_pooled);
    cudaGetSymbolAddress((void**)&counts, g_counts);

    // ---- norm precompute ----
    k_init<<<(N_GRAPHS * HID + 255) / 256, 256>>>(deg, pooled, counts);
    k_count_deg<<<(N_EDGES + 255) / 256, 256>>>(col, deg);
    k_dis<<<(N_NODES + 255) / 256, 256>>>(deg, dis);
    k_edge_w<<<(N_EDGES + 255) / 256, 256>>>(row, col, dis, ew);

    dim3 gemm_grid(HID / 64, (N_NODES + 127) / 128);
    int feat_blocks = (int)(((size_t)N_NODES * HID + 255) / 256);
    int edge_blocks = (N_EDGES + 3) / 4;

    // ---- layer 1 ----
    k_sgemm<false><<<gemm_grid, 256>>>(x, W1, xw, N_NODES, IN_CH);
    k_init_out<<<feat_blocks, 256>>>(xw, dis, b1, hA);
    k_scatter<<<edge_blocks, 256>>>(xw, row, col, ew, hA);

    // ---- layer 2 (relu fused into A-load) ----
    k_sgemm<true><<<gemm_grid, 256>>>(hA, W2, xw, N_NODES, HID);
    k_init_out<<<feat_blocks, 256>>>(xw, dis, b2, hB);
    k_scatter<<<edge_blocks, 256>>>(xw, row, col, ew, hB);

    // ---- layer 3 ----
    k_sgemm<true><<<gemm_grid, 256>>>(hB, W3, xw, N_NODES, HID);
    k_init_out<<<feat_blocks, 256>>>(xw, dis, b3, hA);
    k_scatter<<<edge_blocks, 256>>>(xw, row, col, ew, hA);

    // ---- pooling (relu fused) + FFN ----
    k_counts<<<(N_NODES + 255) / 256, 256>>>(batch, counts);
    k_pool<<<(N_NODES + 3) / 4, 256>>>(hA, batch, pooled);
    k_ffn<<<N_GRAPHS, HID>>>(pooled, counts, Wf, bf, Wo, bo, out);
}

// round 2
// speedup vs baseline: 2.3884x; 2.3884x over previous
#include <cuda_runtime.h>
#include <cstdint>

#define N_NODES 50000
#define N_EDGES 800000
#define N_GRAPHS 256
#define IN_CH 128
#define HID 256

// ---------------- scratch (device globals; no allocation allowed) -------------
__device__ int   g_ideg[N_NODES];
__device__ int   g_off[N_NODES + 1];
__device__ int   g_cursor[N_NODES];
__device__ int   g_src[N_EDGES];
__device__ float g_w[N_EDGES];
__device__ float g_dis[N_NODES];
__device__ float g_xw[(size_t)N_NODES * HID];
__device__ float g_hA[(size_t)N_NODES * HID];
__device__ float g_hB[(size_t)N_NODES * HID];
__device__ float g_pooled[N_GRAPHS * HID];
__device__ float g_counts[N_GRAPHS];

// ---------------- init: zero ideg/cursor/pooled/counts -----------------------
__global__ void k_zero(int* ideg, int* cursor, float* pooled, float* counts) {
    int i = blockIdx.x * blockDim.x + threadIdx.x;
    if (i < N_NODES) { ideg[i] = 0; cursor[i] = 0; }
    if (i < N_GRAPHS * HID) pooled[i] = 0.0f;
    if (i < N_GRAPHS) counts[i] = 0.0f;
}

// ---------------- degree count (col = edge_index[1]) -------------------------
__global__ void k_count(const int* __restrict__ col, int* __restrict__ ideg) {
    int e = blockIdx.x * blockDim.x + threadIdx.x;
    if (e < N_EDGES) atomicAdd(&ideg[col[e]], 1);
}

// ---------------- single-block scan: off = exclusive_prefix(ideg), dis -------
__global__ __launch_bounds__(1024) void k_scan(const int* __restrict__ ideg,
                                               int* __restrict__ off,
                                               float* __restrict__ dis) {
    __shared__ int warpsum[32];
    __shared__ int s_run;
    const int t = threadIdx.x;
    const int lane = t & 31, w = t >> 5;
    if (t == 0) s_run = 0;
    __syncthreads();
    for (int base = 0; base < N_NODES; base += 1024) {
        int i = base + t;
        int v = (i < N_NODES) ? ideg[i] : 0;
        if (i < N_NODES) dis[i] = rsqrtf((float)(v + 1));   // +1 self loop
        // warp inclusive scan
        int inc = v;
#pragma unroll
        for (int s = 1; s < 32; s <<= 1) {
            int u = __shfl_up_sync(0xffffffffu, inc, s);
            if (lane >= s) inc += u;
        }
        if (lane == 31) warpsum[w] = inc;
        __syncthreads();
        if (w == 0) {
            int ws = warpsum[lane];
            int wi = ws;
#pragma unroll
            for (int s = 1; s < 32; s <<= 1) {
                int u = __shfl_up_sync(0xffffffffu, wi, s);
                if (lane >= s) wi += u;
            }
            warpsum[lane] = wi;   // inclusive warp totals
        }
        __syncthreads();
        int woff = (w > 0) ? warpsum[w - 1] : 0;
        int run = s_run;
        if (i < N_NODES) off[i] = run + woff + inc - v;     // exclusive
        int tot = warpsum[31];
        __syncthreads();
        if (t == 0) s_run = run + tot;
        __syncthreads();
    }
    if (t == 0) off[N_NODES] = s_run;
}

// ---------------- fill CSR: place each edge into its dst bucket --------------
__global__ void k_fill(const int* __restrict__ row, const int* __restrict__ col,
                       const int* __restrict__ off, const float* __restrict__ dis,
                       int* __restrict__ cursor,
                       int* __restrict__ srt_src, float* __restrict__ srt_w) {
    int e = blockIdx.x * blockDim.x + threadIdx.x;
    if (e >= N_EDGES) return;
    int r = row[e], c = col[e];
    int pos = off[c] + atomicAdd(&cursor[c], 1);
    srt_src[pos] = r;
    srt_w[pos]   = dis[r] * dis[c];
}

// ---------------- SGEMM: C[M,256] = A[M,K] @ B[K,256] ------------------------
__global__ __launch_bounds__(256) void k_sgemm(const float* __restrict__ A,
                                               const float* __restrict__ B,
                                               float* __restrict__ C,
                                               int M, int K) {
    __shared__ float As[16][128];
    __shared__ float Bs[16][64];
    const int bm = blockIdx.y * 128;
    const int bn = blockIdx.x * 64;
    const int tid = threadIdx.x;
    const int tx = tid % 16;   // n direction (x4)
    const int ty = tid / 16;   // m direction (x8)

    float acc[8][4];
#pragma unroll
    for (int i = 0; i < 8; i++)
#pragma unroll
        for (int j = 0; j < 4; j++) acc[i][j] = 0.0f;

    for (int k0 = 0; k0 < K; k0 += 16) {
#pragma unroll
        for (int l = 0; l < 2; l++) {
            int idx = tid + l * 256;
            int m   = idx >> 2;
            int kk  = (idx & 3) * 4;
            int gm  = bm + m;
            float4 v = make_float4(0.f, 0.f, 0.f, 0.f);
            if (gm < M) v = *(const float4*)&A[(size_t)gm * K + k0 + kk];
            As[kk + 0][m] = v.x; As[kk + 1][m] = v.y;
            As[kk + 2][m] = v.z; As[kk + 3][m] = v.w;
        }
        {
            int kk = tid >> 4;
            int n  = (tid & 15) * 4;
            float4 v = *(const float4*)&B[(size_t)(k0 + kk) * HID + bn + n];
            Bs[kk][n + 0] = v.x; Bs[kk][n + 1] = v.y;
            Bs[kk][n + 2] = v.z; Bs[kk][n + 3] = v.w;
        }
        __syncthreads();
#pragma unroll
        for (int k = 0; k < 16; k++) {
            float a[8], b[4];
#pragma unroll
            for (int i = 0; i < 8; i++) a[i] = As[k][ty * 8 + i];
#pragma unroll
            for (int j = 0; j < 4; j++) b[j] = Bs[k][tx * 4 + j];
#pragma unroll
            for (int i = 0; i < 8; i++)
#pragma unroll
                for (int j = 0; j < 4; j++) acc[i][j] = fmaf(a[i], b[j], acc[i][j]);
        }
        __syncthreads();
    }
#pragma unroll
    for (int i = 0; i < 8; i++) {
        int gm = bm + ty * 8 + i;
        if (gm < M) {
            float4 v = make_float4(acc[i][0], acc[i][1], acc[i][2], acc[i][3]);
            *(float4*)&C[(size_t)gm * HID + bn + tx * 4] = v;
        }
    }
}

// ---------------- aggregate (atomic-free gather) -----------------------------
// out[i] = relu( xw[i]*dis[i]^2 + b + sum_j w_j * xw[src_j] )
// 64 threads per node (float4 per lane), 4 nodes per 256-thread block.
__global__ __launch_bounds__(256) void k_aggregate(const float* __restrict__ xw,
                                                   const int* __restrict__ off,
                                                   const int* __restrict__ srt_src,
                                                   const float* __restrict__ srt_w,
                                                   const float* __restrict__ dis,
                                                   const float* __restrict__ bias,
                                                   float* __restrict__ out) {
    int nid  = blockIdx.x * 4 + (threadIdx.x >> 6);
    int lane = threadIdx.x & 63;
    if (nid >= N_NODES) return;
    float d  = dis[nid];
    float d2 = d * d;
    float4 acc = *(const float4*)&xw[(size_t)nid * HID + lane * 4];
    float4 b   = *(const float4*)&bias[lane * 4];
    acc.x = fmaf(acc.x, d2, b.x); acc.y = fmaf(acc.y, d2, b.y);
    acc.z = fmaf(acc.z, d2, b.z); acc.w = fmaf(acc.w, d2, b.w);
    int s = off[nid], e = off[nid + 1];
    int j = s;
    // 2-wide software pipeline for MLP
    for (; j + 1 < e; j += 2) {
        int   s0 = __ldg(&srt_src[j]),   s1 = __ldg(&srt_src[j + 1]);
        float w0 = __ldg(&srt_w[j]),     w1 = __ldg(&srt_w[j + 1]);
        float4 v0 = *(const float4*)&xw[(size_t)s0 * HID + lane * 4];
        float4 v1 = *(const float4*)&xw[(size_t)s1 * HID + lane * 4];
        acc.x = fmaf(v0.x, w0, acc.x); acc.y = fmaf(v0.y, w0, acc.y);
        acc.z = fmaf(v0.z, w0, acc.z); acc.w = fmaf(v0.w, w0, acc.w);
        acc.x = fmaf(v1.x, w1, acc.x); acc.y = fmaf(v1.y, w1, acc.y);
        acc.z = fmaf(v1.z, w1, acc.z); acc.w = fmaf(v1.w, w1, acc.w);
    }
    if (j < e) {
        int   s0 = __ldg(&srt_src[j]);
        float w0 = __ldg(&srt_w[j]);
        float4 v0 = *(const float4*)&xw[(size_t)s0 * HID + lane * 4];
        acc.x = fmaf(v0.x, w0, acc.x); acc.y = fmaf(v0.y, w0, acc.y);
        acc.z = fmaf(v0.z, w0, acc.z); acc.w = fmaf(v0.w, w0, acc.w);
    }
    // fused ReLU (valid for all 3 layers: next consumer wants relu(h))
    acc.x = fmaxf(acc.x, 0.f); acc.y = fmaxf(acc.y, 0.f);
    acc.z = fmaxf(acc.z, 0.f); acc.w = fmaxf(acc.w, 0.f);
    *(float4*)&out[(size_t)nid * HID + lane * 4] = acc;
}

// ---------------- graph counts -----------------------------------------------
__global__ void k_counts(const int* __restrict__ batch, float* __restrict__ counts) {
    int i = blockIdx.x * blockDim.x + threadIdx.x;
    if (i < N_NODES) atomicAdd(&counts[batch[i]], 1.0f);
}

// ---------------- pool: pooled[batch[i]] += h[i]  (h already relu'd) ---------
__device__ __forceinline__ void red_add_v4(float* addr, float4 v) {
    asm volatile("red.global.add.v4.f32 [%0], {%1,%2,%3,%4};"
                 :: "l"(addr), "f"(v.x), "f"(v.y), "f"(v.z), "f"(v.w)
                 : "memory");
}
__global__ __launch_bounds__(256) void k_pool(const float* __restrict__ h,
                                              const int* __restrict__ batch,
                                              float* __restrict__ pooled) {
    int nid  = blockIdx.x * 4 + (threadIdx.x >> 6);
    int lane = threadIdx.x & 63;
    if (nid >= N_NODES) return;
    int b = batch[nid];
    float4 v = *(const float4*)&h[(size_t)nid * HID + lane * 4];
    red_add_v4(&pooled[(size_t)b * HID + lane * 4], v);
}

// ---------------- FFN --------------------------------------------------------
__global__ __launch_bounds__(256) void k_ffn(const float* __restrict__ pooled,
                                             const float* __restrict__ counts,
                                             const float* __restrict__ Wf,
                                             const float* __restrict__ bf,
                                             const float* __restrict__ Wo,
                                             const float* __restrict__ bo,
                                             float* __restrict__ out) {
    int g = blockIdx.x;
    int t = threadIdx.x;
    __shared__ float prow[HID];
    __shared__ float red[HID];
    float inv = 1.0f / fmaxf(counts[g], 1.0f);
    prow[t] = pooled[g * HID + t] * inv;
    __syncthreads();
    float acc = bf[t];
#pragma unroll 8
    for (int k = 0; k < HID; k++) acc = fmaf(prow[k], Wf[k * HID + t], acc);
    red[t] = fmaxf(acc, 0.0f) * Wo[t];
    __syncthreads();
    for (int s = 128; s > 0; s >>= 1) {
        if (t < s) red[t] += red[t + s];
        __syncthreads();
    }
    if (t == 0) out[g] = red[0] + bo[0];
}

// ---------------- host side ---------------------------------------------------
extern "C" void kernel_launch(void* const* d_in, const int* in_sizes, int n_in,
                              void* d_out, int out_size) {
    const float* x    = (const float*)d_in[0];
    const int*   ei   = (const int*)d_in[1];
    const int*   batch= (const int*)d_in[2];
    const float* W1   = (const float*)d_in[3];
    const float* b1   = (const float*)d_in[4];
    const float* W2   = (const float*)d_in[5];
    const float* b2   = (const float*)d_in[6];
    const float* W3   = (const float*)d_in[7];
    const float* b3   = (const float*)d_in[8];
    const float* Wf   = (const float*)d_in[9];
    const float* bf   = (const float*)d_in[10];
    const float* Wo   = (const float*)d_in[11];
    const float* bo   = (const float*)d_in[12];
    float* out = (float*)d_out;

    const int* row = ei;             // edge_index[0]
    const int* col = ei + N_EDGES;   // edge_index[1]

    int *ideg, *off, *cursor, *srt_src;
    float *srt_w, *dis, *xw, *hA, *hB, *pooled, *counts;
    cudaGetSymbolAddress((void**)&ideg,    g_ideg);
    cudaGetSymbolAddress((void**)&off,     g_off);
    cudaGetSymbolAddress((void**)&cursor,  g_cursor);
    cudaGetSymbolAddress((void**)&srt_src, g_src);
    cudaGetSymbolAddress((void**)&srt_w,   g_w);
    cudaGetSymbolAddress((void**)&dis,     g_dis);
    cudaGetSymbolAddress((void**)&xw,      g_xw);
    cudaGetSymbolAddress((void**)&hA,      g_hA);
    cudaGetSymbolAddress((void**)&hB,      g_hB);
    cudaGetSymbolAddress((void**)&pooled,  g_pooled);
    cudaGetSymbolAddress((void**)&counts,  g_counts);

    // ---- CSR build (once, reused by all 3 layers) ----
    k_zero<<<(N_GRAPHS * HID + 255) / 256, 256>>>(ideg, cursor, pooled, counts);
    k_count<<<(N_EDGES + 255) / 256, 256>>>(col, ideg);
    k_scan<<<1, 1024>>>(ideg, off, dis);
    k_fill<<<(N_EDGES + 255) / 256, 256>>>(row, col, off, dis, cursor, srt_src, srt_w);

    dim3 gemm_grid(HID / 64, (N_NODES + 127) / 128);
    int node_blocks = (N_NODES + 3) / 4;

    // ---- layer 1 ----
    k_sgemm<<<gemm_grid, 256>>>(x, W1, xw, N_NODES, IN_CH);
    k_aggregate<<<node_blocks, 256>>>(xw, off, srt_src, srt_w, dis, b1, hA);
    // ---- layer 2 ----
    k_sgemm<<<gemm_grid, 256>>>(hA, W2, xw, N_NODES, HID);
    k_aggregate<<<node_blocks, 256>>>(xw, off, srt_src, srt_w, dis, b2, hB);
    // ---- layer 3 ----
    k_sgemm<<<gemm_grid, 256>>>(hB, W3, xw, N_NODES, HID);
    k_aggregate<<<node_blocks, 256>>>(xw, off, srt_src, srt_w, dis, b3, hA);

    // ---- pooling + FFN ----
    k_counts<<<(N_NODES + 255) / 256, 256>>>(batch, counts);
    k_pool<<<node_blocks, 256>>>(hA, batch, pooled);
    k_ffn<<<N_GRAPHS, HID>>>(pooled, counts, Wf, bf, Wo, bo, out);
}

// round 3
// speedup vs baseline: 3.7337x; 1.5632x over previous
#include <cuda_runtime.h>
#include <cstdint>

#define N_NODES 50000
#define N_EDGES 800000
#define N_GRAPHS 256
#define IN_CH 128
#define HID 256

// ---------------- scratch (device globals; no allocation allowed) -------------
__device__ int   g_ideg[N_NODES];
__device__ int   g_off[N_NODES + 1];
__device__ int   g_cursor[N_NODES];
__device__ int   g_src[N_EDGES];
__device__ float g_w[N_EDGES];
__device__ float g_dis[N_NODES];
__device__ float g_xt[(size_t)N_NODES * IN_CH];                 // tf32-rounded x
__device__ float g_Wr[(IN_CH + HID + HID) * HID];               // tf32-rounded weights
__device__ float g_xw[(size_t)N_NODES * HID];
__device__ float g_hA[(size_t)N_NODES * HID];
__device__ float g_hB[(size_t)N_NODES * HID];
__device__ float g_pooled[N_GRAPHS * HID];
__device__ float g_counts[N_GRAPHS];

// ---------------- tf32 rounding helpers --------------------------------------
__device__ __forceinline__ float tf32r(float x) {
    uint32_t u;
    asm("cvt.rna.tf32.f32 %0, %1;" : "=r"(u) : "f"(x));
    return __uint_as_float(u);
}

__global__ void k_round4(const float* __restrict__ in, float* __restrict__ out, int n4) {
    int i = blockIdx.x * blockDim.x + threadIdx.x;
    if (i >= n4) return;
    float4 v = ((const float4*)in)[i];
    v.x = tf32r(v.x); v.y = tf32r(v.y); v.z = tf32r(v.z); v.w = tf32r(v.w);
    ((float4*)out)[i] = v;
}

// ---------------- init: zero ideg/cursor/pooled/counts -----------------------
__global__ void k_zero(int* ideg, int* cursor, float* pooled, float* counts) {
    int i = blockIdx.x * blockDim.x + threadIdx.x;
    if (i < N_NODES) { ideg[i] = 0; cursor[i] = 0; }
    if (i < N_GRAPHS * HID) pooled[i] = 0.0f;
    if (i < N_GRAPHS) counts[i] = 0.0f;
}

__global__ void k_count(const int* __restrict__ col, int* __restrict__ ideg) {
    int e = blockIdx.x * blockDim.x + threadIdx.x;
    if (e < N_EDGES) atomicAdd(&ideg[col[e]], 1);
}

// ---------------- single-block scan: off = exclusive_prefix(ideg), dis -------
__global__ __launch_bounds__(1024) void k_scan(const int* __restrict__ ideg,
                                               int* __restrict__ off,
                                               float* __restrict__ dis) {
    __shared__ int warpsum[32];
    __shared__ int s_run;
    const int t = threadIdx.x;
    const int lane = t & 31, w = t >> 5;
    if (t == 0) s_run = 0;
    __syncthreads();
    for (int base = 0; base < N_NODES; base += 1024) {
        int i = base + t;
        int v = (i < N_NODES) ? ideg[i] : 0;
        if (i < N_NODES) dis[i] = rsqrtf((float)(v + 1));
        int inc = v;
#pragma unroll
        for (int s = 1; s < 32; s <<= 1) {
            int u = __shfl_up_sync(0xffffffffu, inc, s);
            if (lane >= s) inc += u;
        }
        if (lane == 31) warpsum[w] = inc;
        __syncthreads();
        if (w == 0) {
            int wi = warpsum[lane];
#pragma unroll
            for (int s = 1; s < 32; s <<= 1) {
                int u = __shfl_up_sync(0xffffffffu, wi, s);
                if (lane >= s) wi += u;
            }
            warpsum[lane] = wi;
        }
        __syncthreads();
        int woff = (w > 0) ? warpsum[w - 1] : 0;
        int run = s_run;
        if (i < N_NODES) off[i] = run + woff + inc - v;
        int tot = warpsum[31];
        __syncthreads();
        if (t == 0) s_run = run + tot;
        __syncthreads();
    }
    if (t == 0) off[N_NODES] = s_run;
}

__global__ void k_fill(const int* __restrict__ row, const int* __restrict__ col,
                       const int* __restrict__ off, const float* __restrict__ dis,
                       int* __restrict__ cursor,
                       int* __restrict__ srt_src, float* __restrict__ srt_w) {
    int e = blockIdx.x * blockDim.x + threadIdx.x;
    if (e >= N_EDGES) return;
    int r = row[e], c = col[e];
    int pos = off[c] + atomicAdd(&cursor[c], 1);
    srt_src[pos] = r;
    srt_w[pos]   = dis[r] * dis[c];
}

// ---------------- TF32 tensor-core GEMM: C[M,256] = A[M,K] @ B[K,256] --------
// BM=128 BN=128 BK=32; 256 threads = 8 warps (4m x 2n); warp tile 32x64.
// Smem strides: A stride 36 (== 4 mod 32), B stride 136 (== 8 mod 32) make
// all scalar fragment loads bank-conflict-free.
#define BM 128
#define BN 128
#define BK 32
#define ASTR 36
#define BSTR 136

__global__ __launch_bounds__(256) void k_mma(const float* __restrict__ A,
                                             const float* __restrict__ B,
                                             float* __restrict__ C,
                                             int M, int K) {
    __shared__ float As[BM * ASTR];   // 18432 B
    __shared__ float Bs[BK * BSTR];   // 17408 B
    const int tid  = threadIdx.x;
    const int warp = tid >> 5, lane = tid & 31;
    const int wm = (warp & 3) * 32;
    const int wn = (warp >> 2) * 64;
    const int r = lane >> 2, c = lane & 3;
    const int bm = blockIdx.y * BM;
    const int bn = blockIdx.x * BN;

    float acc[2][8][4];
#pragma unroll
    for (int mt = 0; mt < 2; mt++)
#pragma unroll
        for (int nt = 0; nt < 8; nt++)
#pragma unroll
            for (int q = 0; q < 4; q++) acc[mt][nt][q] = 0.0f;

    for (int k0 = 0; k0 < K; k0 += BK) {
        // load A tile: 128x32 = 1024 float4, 4 per thread
#pragma unroll
        for (int i = 0; i < 4; i++) {
            int f   = tid + i * 256;
            int row = f >> 3;
            int cg  = (f & 7) * 4;
            int gm  = bm + row;
            float4 v = make_float4(0.f, 0.f, 0.f, 0.f);
            if (gm < M) v = *(const float4*)&A[(size_t)gm * K + k0 + cg];
            *(float4*)&As[row * ASTR + cg] = v;
        }
        // load B tile: 32x128 = 1024 float4, 4 per thread
#pragma unroll
        for (int i = 0; i < 4; i++) {
            int f   = tid + i * 256;
            int row = f >> 5;
            int cg  = (f & 31) * 4;
            float4 v = *(const float4*)&B[(size_t)(k0 + row) * HID + bn + cg];
            *(float4*)&Bs[row * BSTR + cg] = v;
        }
        __syncthreads();
#pragma unroll
        for (int ks = 0; ks < 4; ks++) {
            const int kk = ks * 8;
            uint32_t a[2][4];
#pragma unroll
            for (int mt = 0; mt < 2; mt++) {
                int base = wm + mt * 16;
                a[mt][0] = __float_as_uint(As[(base + r    ) * ASTR + kk + c    ]);
                a[mt][1] = __float_as_uint(As[(base + r + 8) * ASTR + kk + c    ]);
                a[mt][2] = __float_as_uint(As[(base + r    ) * ASTR + kk + c + 4]);
                a[mt][3] = __float_as_uint(As[(base + r + 8) * ASTR + kk + c + 4]);
            }
#pragma unroll
            for (int nt = 0; nt < 8; nt++) {
                uint32_t b0 = __float_as_uint(Bs[(kk + c    ) * BSTR + wn + nt * 8 + r]);
                uint32_t b1 = __float_as_uint(Bs[(kk + c + 4) * BSTR + wn + nt * 8 + r]);
#pragma unroll
                for (int mt = 0; mt < 2; mt++) {
                    asm volatile(
                        "mma.sync.aligned.m16n8k8.row.col.f32.tf32.tf32.f32 "
                        "{%0,%1,%2,%3}, {%4,%5,%6,%7}, {%8,%9}, {%0,%1,%2,%3};"
                        : "+f"(acc[mt][nt][0]), "+f"(acc[mt][nt][1]),
                          "+f"(acc[mt][nt][2]), "+f"(acc[mt][nt][3])
                        : "r"(a[mt][0]), "r"(a[mt][1]), "r"(a[mt][2]), "r"(a[mt][3]),
                          "r"(b0), "r"(b1));
                }
            }
        }
        __syncthreads();
    }
    // epilogue: c0:(r,2c) c1:(r,2c+1) c2:(r+8,2c) c3:(r+8,2c+1)
#pragma unroll
    for (int mt = 0; mt < 2; mt++) {
        int row0 = bm + wm + mt * 16 + r;
#pragma unroll
        for (int nt = 0; nt < 8; nt++) {
            int cc = bn + wn + nt * 8 + 2 * c;
            if (row0 < M)
                *(float2*)&C[(size_t)row0 * HID + cc] =
                    make_float2(acc[mt][nt][0], acc[mt][nt][1]);
            if (row0 + 8 < M)
                *(float2*)&C[(size_t)(row0 + 8) * HID + cc] =
                    make_float2(acc[mt][nt][2], acc[mt][nt][3]);
        }
    }
}

// ---------------- aggregate (atomic-free gather) -----------------------------
// out[i] = tf32( relu( xw[i]*dis^2 + b + sum_j w_j * xw[src_j] ) )
__global__ __launch_bounds__(256) void k_aggregate(const float* __restrict__ xw,
                                                   const int* __restrict__ off,
                                                   const int* __restrict__ srt_src,
                                                   const float* __restrict__ srt_w,
                                                   const float* __restrict__ dis,
                                                   const float* __restrict__ bias,
                                                   float* __restrict__ out) {
    int nid  = blockIdx.x * 4 + (threadIdx.x >> 6);
    int lane = threadIdx.x & 63;
    if (nid >= N_NODES) return;
    float d  = dis[nid];
    float d2 = d * d;
    float4 acc = *(const float4*)&xw[(size_t)nid * HID + lane * 4];
    float4 b   = *(const float4*)&bias[lane * 4];
    acc.x = fmaf(acc.x, d2, b.x); acc.y = fmaf(acc.y, d2, b.y);
    acc.z = fmaf(acc.z, d2, b.z); acc.w = fmaf(acc.w, d2, b.w);
    int s = off[nid], e = off[nid + 1];
    int j = s;
    for (; j + 1 < e; j += 2) {
        int   s0 = __ldg(&srt_src[j]),   s1 = __ldg(&srt_src[j + 1]);
        float w0 = __ldg(&srt_w[j]),     w1 = __ldg(&srt_w[j + 1]);
        float4 v0 = *(const float4*)&xw[(size_t)s0 * HID + lane * 4];
        float4 v1 = *(const float4*)&xw[(size_t)s1 * HID + lane * 4];
        acc.x = fmaf(v0.x, w0, acc.x); acc.y = fmaf(v0.y, w0, acc.y);
        acc.z = fmaf(v0.z, w0, acc.z); acc.w = fmaf(v0.w, w0, acc.w);
        acc.x = fmaf(v1.x, w1, acc.x); acc.y = fmaf(v1.y, w1, acc.y);
        acc.z = fmaf(v1.z, w1, acc.z); acc.w = fmaf(v1.w, w1, acc.w);
    }
    if (j < e) {
        int   s0 = __ldg(&srt_src[j]);
        float w0 = __ldg(&srt_w[j]);
        float4 v0 = *(const float4*)&xw[(size_t)s0 * HID + lane * 4];
        acc.x = fmaf(v0.x, w0, acc.x); acc.y = fmaf(v0.y, w0, acc.y);
        acc.z = fmaf(v0.z, w0, acc.z); acc.w = fmaf(v0.w, w0, acc.w);
    }
    acc.x = tf32r(fmaxf(acc.x, 0.f)); acc.y = tf32r(fmaxf(acc.y, 0.f));
    acc.z = tf32r(fmaxf(acc.z, 0.f)); acc.w = tf32r(fmaxf(acc.w, 0.f));
    *(float4*)&out[(size_t)nid * HID + lane * 4] = acc;
}

// ---------------- graph counts -----------------------------------------------
__global__ void k_counts(const int* __restrict__ batch, float* __restrict__ counts) {
    int i = blockIdx.x * blockDim.x + threadIdx.x;
    if (i < N_NODES) atomicAdd(&counts[batch[i]], 1.0f);
}

// ---------------- pool -------------------------------------------------------
__device__ __forceinline__ void red_add_v4(float* addr, float4 v) {
    asm volatile("red.global.add.v4.f32 [%0], {%1,%2,%3,%4};"
                 :: "l"(addr), "f"(v.x), "f"(v.y), "f"(v.z), "f"(v.w)
                 : "memory");
}
__global__ __launch_bounds__(256) void k_pool(const float* __restrict__ h,
                                              const int* __restrict__ batch,
                                              float* __restrict__ pooled) {
    int nid  = blockIdx.x * 4 + (threadIdx.x >> 6);
    int lane = threadIdx.x & 63;
    if (nid >= N_NODES) return;
    int b = batch[nid];
    float4 v = *(const float4*)&h[(size_t)nid * HID + lane * 4];
    red_add_v4(&pooled[(size_t)b * HID + lane * 4], v);
}

// ---------------- FFN --------------------------------------------------------
__global__ __launch_bounds__(256) void k_ffn(const float* __restrict__ pooled,
                                             const float* __restrict__ counts,
                                             const float* __restrict__ Wf,
                                             const float* __restrict__ bf,
                                             const float* __restrict__ Wo,
                                             const float* __restrict__ bo,
                                             float* __restrict__ out) {
    int g = blockIdx.x;
    int t = threadIdx.x;
    __shared__ float prow[HID];
    __shared__ float red[HID];
    float inv = 1.0f / fmaxf(counts[g], 1.0f);
    prow[t] = pooled[g * HID + t] * inv;
    __syncthreads();
    float acc = bf[t];
#pragma unroll 8
    for (int k = 0; k < HID; k++) acc = fmaf(prow[k], Wf[k * HID + t], acc);
    red[t] = fmaxf(acc, 0.0f) * Wo[t];
    __syncthreads();
    for (int s = 128; s > 0; s >>= 1) {
        if (t < s) red[t] += red[t + s];
        __syncthreads();
    }
    if (t == 0) out[g] = red[0] + bo[0];
}

// ---------------- host side ---------------------------------------------------
extern "C" void kernel_launch(void* const* d_in, const int* in_sizes, int n_in,
                              void* d_out, int out_size) {
    const float* x    = (const float*)d_in[0];
    const int*   ei   = (const int*)d_in[1];
    const int*   batch= (const int*)d_in[2];
    const float* W1   = (const float*)d_in[3];
    const float* b1   = (const float*)d_in[4];
    const float* W2   = (const float*)d_in[5];
    const float* b2   = (const float*)d_in[6];
    const float* W3   = (const float*)d_in[7];
    const float* b3   = (const float*)d_in[8];
    const float* Wf   = (const float*)d_in[9];
    const float* bf   = (const float*)d_in[10];
    const float* Wo   = (const float*)d_in[11];
    const float* bo   = (const float*)d_in[12];
    float* out = (float*)d_out;

    const int* row = ei;
    const int* col = ei + N_EDGES;

    int *ideg, *off, *cursor, *srt_src;
    float *srt_w, *dis, *xt, *Wr, *xw, *hA, *hB, *pooled, *counts;
    cudaGetSymbolAddress((void**)&ideg,    g_ideg);
    cudaGetSymbolAddress((void**)&off,     g_off);
    cudaGetSymbolAddress((void**)&cursor,  g_cursor);
    cudaGetSymbolAddress((void**)&srt_src, g_src);
    cudaGetSymbolAddress((void**)&srt_w,   g_w);
    cudaGetSymbolAddress((void**)&dis,     g_dis);
    cudaGetSymbolAddress((void**)&xt,      g_xt);
    cudaGetSymbolAddress((void**)&Wr,      g_Wr);
    cudaGetSymbolAddress((void**)&xw,      g_xw);
    cudaGetSymbolAddress((void**)&hA,      g_hA);
    cudaGetSymbolAddress((void**)&hB,      g_hB);
    cudaGetSymbolAddress((void**)&pooled,  g_pooled);
    cudaGetSymbolAddress((void**)&counts,  g_counts);

    float* Wr1 = Wr;
    float* Wr2 = Wr + IN_CH * HID;
    float* Wr3 = Wr2 + HID * HID;

    // ---- CSR build ----
    k_zero<<<(N_GRAPHS * HID + 255) / 256, 256>>>(ideg, cursor, pooled, counts);
    k_count<<<(N_EDGES + 255) / 256, 256>>>(col, ideg);
    k_scan<<<1, 1024>>>(ideg, off, dis);
    k_fill<<<(N_EDGES + 255) / 256, 256>>>(row, col, off, dis, cursor, srt_src, srt_w);

    // ---- tf32 rounding of GEMM inputs ----
    k_round4<<<(N_NODES * IN_CH / 4 + 255) / 256, 256>>>(x,  xt,  N_NODES * IN_CH / 4);
    k_round4<<<(IN_CH * HID / 4 + 255) / 256, 256>>>(W1, Wr1, IN_CH * HID / 4);
    k_round4<<<(HID * HID / 4 + 255) / 256, 256>>>(W2, Wr2, HID * HID / 4);
    k_round4<<<(HID * HID / 4 + 255) / 256, 256>>>(W3, Wr3, HID * HID / 4);

    dim3 gemm_grid(HID / BN, (N_NODES + BM - 1) / BM);
    int node_blocks = (N_NODES + 3) / 4;

    // ---- layer 1 ----
    k_mma<<<gemm_grid, 256>>>(xt, Wr1, xw, N_NODES, IN_CH);
    k_aggregate<<<node_blocks, 256>>>(xw, off, srt_src, srt_w, dis, b1, hA);
    // ---- layer 2 ----
    k_mma<<<gemm_grid, 256>>>(hA, Wr2, xw, N_NODES, HID);
    k_aggregate<<<node_blocks, 256>>>(xw, off, srt_src, srt_w, dis, b2, hB);
    // ---- layer 3 ----
    k_mma<<<gemm_grid, 256>>>(hB, Wr3, xw, N_NODES, HID);
    k_aggregate<<<node_blocks, 256>>>(xw, off, srt_src, srt_w, dis, b3, hA);

    // ---- pooling + FFN ----
    k_counts<<<(N_NODES + 255) / 256, 256>>>(batch, counts);
    k_pool<<<node_blocks, 256>>>(hA, batch, pooled);
    k_ffn<<<N_GRAPHS, HID>>>(pooled, counts, Wf, bf, Wo, bo, out);
}

// round 4
// speedup vs baseline: 5.0930x; 1.3641x over previous
#include <cuda_runtime.h>
#include <cuda_fp16.h>
#include <cstdint>

#define N_NODES 50000
#define N_EDGES 800000
#define N_GRAPHS 256
#define IN_CH 128
#define HID 256

// ---------------- scratch (device globals; no allocation allowed) -------------
__device__ int   g_ideg[N_NODES];
__device__ int   g_off[N_NODES + 1];
__device__ int   g_cursor[N_NODES];
__device__ int   g_src[N_EDGES];
__device__ float g_w[N_EDGES];
__device__ float g_dis[N_NODES];
__device__ __align__(16) __half g_xh[(size_t)N_NODES * IN_CH];
__device__ __align__(16) __half g_Wt[(IN_CH + HID + HID) * HID];  // transposed fp16 weights
__device__ __align__(16) __half g_xw[(size_t)N_NODES * HID];
__device__ __align__(16) __half g_hA[(size_t)N_NODES * HID];
__device__ __align__(16) __half g_hB[(size_t)N_NODES * HID];
__device__ float g_pooled[N_GRAPHS * HID];
__device__ float g_counts[N_GRAPHS];

// ---------------- helpers ----------------------------------------------------
__device__ __forceinline__ void red_add_v4(float* addr, float4 v) {
    asm volatile("red.global.add.v4.f32 [%0], {%1,%2,%3,%4};"
                 :: "l"(addr), "f"(v.x), "f"(v.y), "f"(v.z), "f"(v.w)
                 : "memory");
}

__device__ __forceinline__ void h8f(uint4 v, float* f) {
    float2 p0 = __half22float2(*(const __half2*)&v.x);
    float2 p1 = __half22float2(*(const __half2*)&v.y);
    float2 p2 = __half22float2(*(const __half2*)&v.z);
    float2 p3 = __half22float2(*(const __half2*)&v.w);
    f[0] = p0.x; f[1] = p0.y; f[2] = p1.x; f[3] = p1.y;
    f[4] = p2.x; f[5] = p2.y; f[6] = p3.x; f[7] = p3.y;
}

// ---------------- conversions -------------------------------------------------
__global__ void k_f2h(const float* __restrict__ in, __half* __restrict__ out, int n4) {
    int i = blockIdx.x * blockDim.x + threadIdx.x;
    if (i >= n4) return;
    float4 v = ((const float4*)in)[i];
    ((__half2*)out)[i * 2]     = __floats2half2_rn(v.x, v.y);
    ((__half2*)out)[i * 2 + 1] = __floats2half2_rn(v.z, v.w);
}

// W[K,N] fp32 -> Wt[N,K] fp16
__global__ void k_wtrans(const float* __restrict__ W, __half* __restrict__ Wt, int K, int N) {
    int idx = blockIdx.x * blockDim.x + threadIdx.x;
    if (idx >= K * N) return;
    int k = idx / N, n = idx - k * N;
    Wt[(size_t)n * K + k] = __float2half(W[idx]);
}

// ---------------- CSR build ---------------------------------------------------
__global__ void k_zero(int* ideg, int* cursor, float* pooled, float* counts) {
    int i = blockIdx.x * blockDim.x + threadIdx.x;
    if (i < N_NODES) { ideg[i] = 0; cursor[i] = 0; }
    if (i < N_GRAPHS * HID) pooled[i] = 0.0f;
    if (i < N_GRAPHS) counts[i] = 0.0f;
}

__global__ void k_count(const int* __restrict__ col, int* __restrict__ ideg) {
    int e = blockIdx.x * blockDim.x + threadIdx.x;
    if (e < N_EDGES) atomicAdd(&ideg[col[e]], 1);
}

__global__ __launch_bounds__(1024) void k_scan(const int* __restrict__ ideg,
                                               int* __restrict__ off,
                                               float* __restrict__ dis) {
    __shared__ int warpsum[32];
    __shared__ int s_run;
    const int t = threadIdx.x;
    const int lane = t & 31, w = t >> 5;
    if (t == 0) s_run = 0;
    __syncthreads();
    for (int base = 0; base < N_NODES; base += 1024) {
        int i = base + t;
        int v = (i < N_NODES) ? ideg[i] : 0;
        if (i < N_NODES) dis[i] = rsqrtf((float)(v + 1));
        int inc = v;
#pragma unroll
        for (int s = 1; s < 32; s <<= 1) {
            int u = __shfl_up_sync(0xffffffffu, inc, s);
            if (lane >= s) inc += u;
        }
        if (lane == 31) warpsum[w] = inc;
        __syncthreads();
        if (w == 0) {
            int wi = warpsum[lane];
#pragma unroll
            for (int s = 1; s < 32; s <<= 1) {
                int u = __shfl_up_sync(0xffffffffu, wi, s);
                if (lane >= s) wi += u;
            }
            warpsum[lane] = wi;
        }
        __syncthreads();
        int woff = (w > 0) ? warpsum[w - 1] : 0;
        int run = s_run;
        if (i < N_NODES) off[i] = run + woff + inc - v;
        int tot = warpsum[31];
        __syncthreads();
        if (t == 0) s_run = run + tot;
        __syncthreads();
    }
    if (t == 0) off[N_NODES] = s_run;
}

__global__ void k_fill(const int* __restrict__ row, const int* __restrict__ col,
                       const int* __restrict__ off, const float* __restrict__ dis,
                       int* __restrict__ cursor,
                       int* __restrict__ srt_src, float* __restrict__ srt_w) {
    int e = blockIdx.x * blockDim.x + threadIdx.x;
    if (e >= N_EDGES) return;
    int r = row[e], c = col[e];
    int pos = off[c] + atomicAdd(&cursor[c], 1);
    srt_src[pos] = r;
    srt_w[pos]   = dis[r] * dis[c];
}

// ---------------- FP16 tensor-core GEMM: C[M,256] = A[M,K] @ Bt[N,K]^T -------
// BM=128 BN=128 BK=32; 8 warps (4m x 2n); warp tile 32x64 via m16n8k16.
// Smem stride 72 halves (word stride 36 == 4 mod 32): conflict-free fragments.
#define BM 128
#define BN 128
#define BK 32
#define SSTR 72

__global__ __launch_bounds__(256) void k_hgemm(const __half* __restrict__ A,
                                               const __half* __restrict__ Bt,
                                               __half* __restrict__ C,
                                               int M, int K) {
    __shared__ __half As[BM * SSTR];
    __shared__ __half Bs[BN * SSTR];
    const int tid  = threadIdx.x;
    const int warp = tid >> 5, lane = tid & 31;
    const int wm = (warp & 3) * 32;
    const int wn = (warp >> 2) * 64;
    const int r = lane >> 2, c = lane & 3;
    const int bm = blockIdx.y * BM;
    const int bn = blockIdx.x * BN;

    float acc[2][8][4];
#pragma unroll
    for (int mt = 0; mt < 2; mt++)
#pragma unroll
        for (int nt = 0; nt < 8; nt++)
#pragma unroll
            for (int q = 0; q < 4; q++) acc[mt][nt][q] = 0.0f;

    for (int k0 = 0; k0 < K; k0 += BK) {
        // A tile: 128 rows x 32 halves = 512 uint4, 2 per thread
#pragma unroll
        for (int i = 0; i < 2; i++) {
            int f   = tid + i * 256;
            int row = f >> 2;
            int cg  = (f & 3) * 8;
            int gm  = bm + row;
            uint4 v = make_uint4(0u, 0u, 0u, 0u);
            if (gm < M) v = *(const uint4*)&A[(size_t)gm * K + k0 + cg];
            *(uint4*)&As[row * SSTR + cg] = v;
        }
        // B tile: 128 n-rows x 32 k-halves from Bt[N,K]
#pragma unroll
        for (int i = 0; i < 2; i++) {
            int f   = tid + i * 256;
            int row = f >> 2;
            int cg  = (f & 3) * 8;
            uint4 v = *(const uint4*)&Bt[(size_t)(bn + row) * K + k0 + cg];
            *(uint4*)&Bs[row * SSTR + cg] = v;
        }
        __syncthreads();
#pragma unroll
        for (int ks = 0; ks < 2; ks++) {
            const int kk = ks * 16;
            uint32_t a[2][4];
#pragma unroll
            for (int mt = 0; mt < 2; mt++) {
                int base = wm + mt * 16;
                a[mt][0] = *(const uint32_t*)&As[(base + r    ) * SSTR + kk + 2 * c];
                a[mt][1] = *(const uint32_t*)&As[(base + r + 8) * SSTR + kk + 2 * c];
                a[mt][2] = *(const uint32_t*)&As[(base + r    ) * SSTR + kk + 8 + 2 * c];
                a[mt][3] = *(const uint32_t*)&As[(base + r + 8) * SSTR + kk + 8 + 2 * c];
            }
#pragma unroll
            for (int nt = 0; nt < 8; nt++) {
                uint32_t b0 = *(const uint32_t*)&Bs[(wn + nt * 8 + r) * SSTR + kk + 2 * c];
                uint32_t b1 = *(const uint32_t*)&Bs[(wn + nt * 8 + r) * SSTR + kk + 8 + 2 * c];
#pragma unroll
                for (int mt = 0; mt < 2; mt++) {
                    asm volatile(
                        "mma.sync.aligned.m16n8k16.row.col.f32.f16.f16.f32 "
                        "{%0,%1,%2,%3}, {%4,%5,%6,%7}, {%8,%9}, {%0,%1,%2,%3};"
                        : "+f"(acc[mt][nt][0]), "+f"(acc[mt][nt][1]),
                          "+f"(acc[mt][nt][2]), "+f"(acc[mt][nt][3])
                        : "r"(a[mt][0]), "r"(a[mt][1]), "r"(a[mt][2]), "r"(a[mt][3]),
                          "r"(b0), "r"(b1));
                }
            }
        }
        __syncthreads();
    }
    // epilogue: c0:(r,2c) c1:(r,2c+1) c2:(r+8,2c) c3:(r+8,2c+1) -> half2 stores
#pragma unroll
    for (int mt = 0; mt < 2; mt++) {
        int row0 = bm + wm + mt * 16 + r;
#pragma unroll
        for (int nt = 0; nt < 8; nt++) {
            int cc = bn + wn + nt * 8 + 2 * c;
            if (row0 < M)
                *(__half2*)&C[(size_t)row0 * HID + cc] =
                    __floats2half2_rn(acc[mt][nt][0], acc[mt][nt][1]);
            if (row0 + 8 < M)
                *(__half2*)&C[(size_t)(row0 + 8) * HID + cc] =
                    __floats2half2_rn(acc[mt][nt][2], acc[mt][nt][3]);
        }
    }
}

// ---------------- aggregate (atomic-free gather, fp16 features) --------------
// acc = xw[i]*dis^2 + b + sum_j w_j * xw[src_j];  relu;
// POOL=false: write fp16 row.  POOL=true: red.add into pooled[batch[i]].
template <bool POOL>
__global__ __launch_bounds__(256) void k_aggregate_h(const __half* __restrict__ xw,
                                                     const int* __restrict__ off,
                                                     const int* __restrict__ srt_src,
                                                     const float* __restrict__ srt_w,
                                                     const float* __restrict__ dis,
                                                     const float* __restrict__ bias,
                                                     __half* __restrict__ out,
                                                     const int* __restrict__ batch,
                                                     float* __restrict__ pooled) {
    int nid  = blockIdx.x * 8 + (threadIdx.x >> 5);
    int lane = threadIdx.x & 31;
    if (nid >= N_NODES) return;
    float d  = dis[nid];
    float d2 = d * d;
    float f[8], acc[8];
    uint4 sv = *(const uint4*)&xw[(size_t)nid * HID + lane * 8];
    h8f(sv, f);
    float4 b0 = *(const float4*)&bias[lane * 8];
    float4 b1 = *(const float4*)&bias[lane * 8 + 4];
    acc[0] = fmaf(f[0], d2, b0.x); acc[1] = fmaf(f[1], d2, b0.y);
    acc[2] = fmaf(f[2], d2, b0.z); acc[3] = fmaf(f[3], d2, b0.w);
    acc[4] = fmaf(f[4], d2, b1.x); acc[5] = fmaf(f[5], d2, b1.y);
    acc[6] = fmaf(f[6], d2, b1.z); acc[7] = fmaf(f[7], d2, b1.w);
    int s = off[nid], e = off[nid + 1];
    int j = s;
    for (; j + 1 < e; j += 2) {
        int   s0 = __ldg(&srt_src[j]),   s1 = __ldg(&srt_src[j + 1]);
        float w0 = __ldg(&srt_w[j]),     w1 = __ldg(&srt_w[j + 1]);
        uint4 v0 = *(const uint4*)&xw[(size_t)s0 * HID + lane * 8];
        uint4 v1 = *(const uint4*)&xw[(size_t)s1 * HID + lane * 8];
        float g0[8], g1[8];
        h8f(v0, g0); h8f(v1, g1);
#pragma unroll
        for (int q = 0; q < 8; q++) acc[q] = fmaf(g0[q], w0, acc[q]);
#pragma unroll
        for (int q = 0; q < 8; q++) acc[q] = fmaf(g1[q], w1, acc[q]);
    }
    if (j < e) {
        int   s0 = __ldg(&srt_src[j]);
        float w0 = __ldg(&srt_w[j]);
        uint4 v0 = *(const uint4*)&xw[(size_t)s0 * HID + lane * 8];
        float g0[8];
        h8f(v0, g0);
#pragma unroll
        for (int q = 0; q < 8; q++) acc[q] = fmaf(g0[q], w0, acc[q]);
    }
#pragma unroll
    for (int q = 0; q < 8; q++) acc[q] = fmaxf(acc[q], 0.0f);
    if (POOL) {
        int bg = batch[nid];
        red_add_v4(&pooled[(size_t)bg * HID + lane * 8],
                   make_float4(acc[0], acc[1], acc[2], acc[3]));
        red_add_v4(&pooled[(size_t)bg * HID + lane * 8 + 4],
                   make_float4(acc[4], acc[5], acc[6], acc[7]));
    } else {
        uint4 o;
        *(__half2*)&o.x = __floats2half2_rn(acc[0], acc[1]);
        *(__half2*)&o.y = __floats2half2_rn(acc[2], acc[3]);
        *(__half2*)&o.z = __floats2half2_rn(acc[4], acc[5]);
        *(__half2*)&o.w = __floats2half2_rn(acc[6], acc[7]);
        *(uint4*)&out[(size_t)nid * HID + lane * 8] = o;
    }
}

// ---------------- graph counts -----------------------------------------------
__global__ void k_counts(const int* __restrict__ batch, float* __restrict__ counts) {
    int i = blockIdx.x * blockDim.x + threadIdx.x;
    if (i < N_NODES) atomicAdd(&counts[batch[i]], 1.0f);
}

// ---------------- FFN --------------------------------------------------------
__global__ __launch_bounds__(256) void k_ffn(const float* __restrict__ pooled,
                                             const float* __restrict__ counts,
                                             const float* __restrict__ Wf,
                                             const float* __restrict__ bf,
                                             const float* __restrict__ Wo,
                                             const float* __restrict__ bo,
                                             float* __restrict__ out) {
    int g = blockIdx.x;
    int t = threadIdx.x;
    __shared__ float prow[HID];
    __shared__ float red[HID];
    float inv = 1.0f / fmaxf(counts[g], 1.0f);
    prow[t] = pooled[g * HID + t] * inv;
    __syncthreads();
    float acc = bf[t];
#pragma unroll 8
    for (int k = 0; k < HID; k++) acc = fmaf(prow[k], Wf[k * HID + t], acc);
    red[t] = fmaxf(acc, 0.0f) * Wo[t];
    __syncthreads();
    for (int s = 128; s > 0; s >>= 1) {
        if (t < s) red[t] += red[t + s];
        __syncthreads();
    }
    if (t == 0) out[g] = red[0] + bo[0];
}

// ---------------- host side ---------------------------------------------------
extern "C" void kernel_launch(void* const* d_in, const int* in_sizes, int n_in,
                              void* d_out, int out_size) {
    const float* x    = (const float*)d_in[0];
    const int*   ei   = (const int*)d_in[1];
    const int*   batch= (const int*)d_in[2];
    const float* W1   = (const float*)d_in[3];
    const float* b1   = (const float*)d_in[4];
    const float* W2   = (const float*)d_in[5];
    const float* b2   = (const float*)d_in[6];
    const float* W3   = (const float*)d_in[7];
    const float* b3   = (const float*)d_in[8];
    const float* Wf   = (const float*)d_in[9];
    const float* bf   = (const float*)d_in[10];
    const float* Wo   = (const float*)d_in[11];
    const float* bo   = (const float*)d_in[12];
    float* out = (float*)d_out;

    const int* row = ei;
    const int* col = ei + N_EDGES;

    int *ideg, *off, *cursor, *srt_src;
    float *srt_w, *dis, *pooled, *counts;
    __half *xh, *Wt, *xw, *hA, *hB;
    cudaGetSymbolAddress((void**)&ideg,    g_ideg);
    cudaGetSymbolAddress((void**)&off,     g_off);
    cudaGetSymbolAddress((void**)&cursor,  g_cursor);
    cudaGetSymbolAddress((void**)&srt_src, g_src);
    cudaGetSymbolAddress((void**)&srt_w,   g_w);
    cudaGetSymbolAddress((void**)&dis,     g_dis);
    cudaGetSymbolAddress((void**)&xh,      g_xh);
    cudaGetSymbolAddress((void**)&Wt,      g_Wt);
    cudaGetSymbolAddress((void**)&xw,      g_xw);
    cudaGetSymbolAddress((void**)&hA,      g_hA);
    cudaGetSymbolAddress((void**)&hB,      g_hB);
    cudaGetSymbolAddress((void**)&pooled,  g_pooled);
    cudaGetSymbolAddress((void**)&counts,  g_counts);

    __half* Wt1 = Wt;
    __half* Wt2 = Wt + IN_CH * HID;
    __half* Wt3 = Wt2 + HID * HID;

    // ---- CSR build ----
    k_zero<<<(N_GRAPHS * HID + 255) / 256, 256>>>(ideg, cursor, pooled, counts);
    k_count<<<(N_EDGES + 255) / 256, 256>>>(col, ideg);
    k_scan<<<1, 1024>>>(ideg, off, dis);
    k_fill<<<(N_EDGES + 255) / 256, 256>>>(row, col, off, dis, cursor, srt_src, srt_w);

    // ---- fp16 conversions ----
    k_f2h<<<(N_NODES * IN_CH / 4 + 255) / 256, 256>>>(x, xh, N_NODES * IN_CH / 4);
    k_wtrans<<<(IN_CH * HID + 255) / 256, 256>>>(W1, Wt1, IN_CH, HID);
    k_wtrans<<<(HID * HID + 255) / 256, 256>>>(W2, Wt2, HID, HID);
    k_wtrans<<<(HID * HID + 255) / 256, 256>>>(W3, Wt3, HID, HID);

    dim3 gemm_grid(HID / BN, (N_NODES + BM - 1) / BM);
    int node_blocks = (N_NODES + 7) / 8;

    // ---- layer 1 ----
    k_hgemm<<<gemm_grid, 256>>>(xh, Wt1, xw, N_NODES, IN_CH);
    k_aggregate_h<false><<<node_blocks, 256>>>(xw, off, srt_src, srt_w, dis, b1,
                                               hA, batch, pooled);
    // ---- layer 2 ----
    k_hgemm<<<gemm_grid, 256>>>(hA, Wt2, xw, N_NODES, HID);
    k_aggregate_h<false><<<node_blocks, 256>>>(xw, off, srt_src, srt_w, dis, b2,
                                               hB, batch, pooled);
    // ---- layer 3 (pool fused) ----
    k_hgemm<<<gemm_grid, 256>>>(hB, Wt3, xw, N_NODES, HID);
    k_aggregate_h<true><<<node_blocks, 256>>>(xw, off, srt_src, srt_w, dis, b3,
                                              hA, batch, pooled);

    // ---- counts + FFN ----
    k_counts<<<(N_NODES + 255) / 256, 256>>>(batch, counts);
    k_ffn<<<N_GRAPHS, HID>>>(pooled, counts, Wf, bf, Wo, bo, out);
}

// round 5
// speedup vs baseline: 6.0766x; 1.1931x over previous
#include <cuda_runtime.h>
#include <cuda_fp16.h>
#include <cstdint>

#define N_NODES 50000
#define N_EDGES 800000
#define N_GRAPHS 256
#define IN_CH 128
#define HID 256
#define NB 49   // scan blocks of 1024

// ---------------- scratch (device globals; no allocation allowed) -------------
__device__ int   g_ideg[N_NODES];
__device__ int   g_off[N_NODES + 1];
__device__ int   g_cursor[N_NODES];
__device__ int   g_bsum[NB];
__device__ int   g_boff[NB];
__device__ __align__(16) int2 g_edge[N_EDGES];   // {src, w-as-int}
__device__ float g_dis[N_NODES];
__device__ __align__(16) __half g_xh[(size_t)N_NODES * IN_CH];
__device__ __align__(16) __half g_Wt[(IN_CH + HID + HID) * HID];
__device__ __align__(16) __half g_xw[(size_t)N_NODES * HID];
__device__ __align__(16) __half g_hA[(size_t)N_NODES * HID];
__device__ __align__(16) __half g_hB[(size_t)N_NODES * HID];
__device__ float g_pooled[N_GRAPHS * HID];
__device__ float g_counts[N_GRAPHS];

// ---------------- helpers ----------------------------------------------------
__device__ __forceinline__ void red_add_v4(float* addr, float4 v) {
    asm volatile("red.global.add.v4.f32 [%0], {%1,%2,%3,%4};"
                 :: "l"(addr), "f"(v.x), "f"(v.y), "f"(v.z), "f"(v.w)
                 : "memory");
}

__device__ __forceinline__ void h8f(uint4 v, float* f) {
    float2 p0 = __half22float2(*(const __half2*)&v.x);
    float2 p1 = __half22float2(*(const __half2*)&v.y);
    float2 p2 = __half22float2(*(const __half2*)&v.z);
    float2 p3 = __half22float2(*(const __half2*)&v.w);
    f[0] = p0.x; f[1] = p0.y; f[2] = p1.x; f[3] = p1.y;
    f[4] = p2.x; f[5] = p2.y; f[6] = p3.x; f[7] = p3.y;
}

// ---------------- fused prep: x->fp16, W1/W2/W3 -> transposed fp16 -----------
#define XF4   (N_NODES * IN_CH / 4)          // 1,600,000
#define W1E   (IN_CH * HID)                  // 32768
#define W23E  (HID * HID)                    // 65536
__global__ void k_prep(const float* __restrict__ x, __half* __restrict__ xh,
                       const float* __restrict__ W1, const float* __restrict__ W2,
                       const float* __restrict__ W3, __half* __restrict__ Wt) {
    int i = blockIdx.x * blockDim.x + threadIdx.x;
    if (i < XF4) {
        float4 v = ((const float4*)x)[i];
        ((__half2*)xh)[i * 2]     = __floats2half2_rn(v.x, v.y);
        ((__half2*)xh)[i * 2 + 1] = __floats2half2_rn(v.z, v.w);
        return;
    }
    i -= XF4;
    if (i < W1E) {                       // W1[K=128,N=256] -> Wt1[N,K]
        int k = i >> 8, n = i & 255;
        Wt[(size_t)n * IN_CH + k] = __float2half(W1[i]);
        return;
    }
    i -= W1E;
    if (i < W23E) {
        int k = i >> 8, n = i & 255;
        Wt[W1E + (size_t)n * HID + k] = __float2half(W2[i]);
        return;
    }
    i -= W23E;
    if (i < W23E) {
        int k = i >> 8, n = i & 255;
        Wt[W1E + W23E + (size_t)n * HID + k] = __float2half(W3[i]);
    }
}

// ---------------- CSR build ---------------------------------------------------
__global__ void k_zero(int* ideg, float* pooled, float* counts) {
    int i = blockIdx.x * blockDim.x + threadIdx.x;
    if (i < N_NODES) ideg[i] = 0;
    if (i < N_GRAPHS * HID) pooled[i] = 0.0f;
    if (i < N_GRAPHS) counts[i] = 0.0f;
}

// degree count + batch counts in one pass
__global__ void k_count(const int* __restrict__ col, int* __restrict__ ideg,
                        const int* __restrict__ batch, float* __restrict__ counts) {
    int e = blockIdx.x * blockDim.x + threadIdx.x;
    if (e < N_EDGES) atomicAdd(&ideg[col[e]], 1);
    if (e < N_NODES) atomicAdd(&counts[batch[e]], 1.0f);
}

// scan stage A: per-1024-block sums
__global__ __launch_bounds__(256) void k_scanA(const int* __restrict__ ideg,
                                               int* __restrict__ bsum) {
    __shared__ int ws[8];
    int b = blockIdx.x, t = threadIdx.x;
    int base = b * 1024 + t * 4;
    int s = 0;
#pragma unroll
    for (int q = 0; q < 4; q++) {
        int i = base + q;
        if (i < N_NODES) s += ideg[i];
    }
#pragma unroll
    for (int o = 16; o; o >>= 1) s += __shfl_down_sync(0xffffffffu, s, o);
    if ((t & 31) == 0) ws[t >> 5] = s;
    __syncthreads();
    if (t < 8) {
        int v = ws[t];
#pragma unroll
        for (int o = 4; o; o >>= 1) v += __shfl_down_sync(0xffu, v, o);
        if (t == 0) bsum[b] = v;
    }
}

// scan stage B: serial scan of NB block sums (tiny)
__global__ void k_scanB(const int* __restrict__ bsum, int* __restrict__ boff,
                        int* __restrict__ off) {
    int run = 0;
    for (int i = 0; i < NB; i++) { boff[i] = run; run += bsum[i]; }
    off[N_NODES] = run;
}

// scan stage C: in-block scan + global offset; writes off, cursor, dis
__global__ __launch_bounds__(1024) void k_scanC(const int* __restrict__ ideg,
                                                const int* __restrict__ boff,
                                                int* __restrict__ off,
                                                int* __restrict__ cursor,
                                                float* __restrict__ dis) {
    __shared__ int warpsum[32];
    int t = threadIdx.x;
    int lane = t & 31, w = t >> 5;
    int i = blockIdx.x * 1024 + t;
    int v = (i < N_NODES) ? ideg[i] : 0;
    int inc = v;
#pragma unroll
    for (int s = 1; s < 32; s <<= 1) {
        int u = __shfl_up_sync(0xffffffffu, inc, s);
        if (lane >= s) inc += u;
    }
    if (lane == 31) warpsum[w] = inc;
    __syncthreads();
    if (w == 0) {
        int wi = warpsum[lane];
#pragma unroll
        for (int s = 1; s < 32; s <<= 1) {
            int u = __shfl_up_sync(0xffffffffu, wi, s);
            if (lane >= s) wi += u;
        }
        warpsum[lane] = wi;
    }
    __syncthreads();
    int woff = (w > 0) ? warpsum[w - 1] : 0;
    if (i < N_NODES) {
        int e = boff[blockIdx.x] + woff + inc - v;
        off[i] = e;
        cursor[i] = e;
        dis[i] = rsqrtf((float)(v + 1));
    }
}

__global__ void k_fill(const int* __restrict__ row, const int* __restrict__ col,
                       const float* __restrict__ dis,
                       int* __restrict__ cursor, int2* __restrict__ edge) {
    int e = blockIdx.x * blockDim.x + threadIdx.x;
    if (e >= N_EDGES) return;
    int r = row[e], c = col[e];
    int pos = atomicAdd(&cursor[c], 1);
    edge[pos] = make_int2(r, __float_as_int(dis[r] * dis[c]));
}

// ---------------- FP16 tensor-core GEMM with register-prefetch pipeline ------
#define BM 128
#define BN 128
#define BK 32
#define SSTR 72

__global__ __launch_bounds__(256) void k_hgemm(const __half* __restrict__ A,
                                               const __half* __restrict__ Bt,
                                               __half* __restrict__ C,
                                               int M, int K) {
    __shared__ __half As[BM * SSTR];
    __shared__ __half Bs[BN * SSTR];
    const int tid  = threadIdx.x;
    const int warp = tid >> 5, lane = tid & 31;
    const int wm = (warp & 3) * 32;
    const int wn = (warp >> 2) * 64;
    const int r = lane >> 2, c = lane & 3;
    const int bm = blockIdx.y * BM;
    const int bn = blockIdx.x * BN;

    // per-thread staging coordinates (2 uint4 each for A and B)
    const int arow0 = (tid) >> 2,        acg0 = ((tid) & 3) * 8;
    const int arow1 = (tid + 256) >> 2,  acg1 = ((tid + 256) & 3) * 8;

    float acc[2][8][4];
#pragma unroll
    for (int mt = 0; mt < 2; mt++)
#pragma unroll
        for (int nt = 0; nt < 8; nt++)
#pragma unroll
            for (int q = 0; q < 4; q++) acc[mt][nt][q] = 0.0f;

    uint4 pa0, pa1, pb0, pb1;
    // prologue loads (k0 = 0)
    {
        int gm0 = bm + arow0, gm1 = bm + arow1;
        pa0 = (gm0 < M) ? *(const uint4*)&A[(size_t)gm0 * K + acg0] : make_uint4(0,0,0,0);
        pa1 = (gm1 < M) ? *(const uint4*)&A[(size_t)gm1 * K + acg1] : make_uint4(0,0,0,0);
        pb0 = *(const uint4*)&Bt[(size_t)(bn + arow0) * K + acg0];
        pb1 = *(const uint4*)&Bt[(size_t)(bn + arow1) * K + acg1];
    }

    for (int k0 = 0; k0 < K; k0 += BK) {
        *(uint4*)&As[arow0 * SSTR + acg0] = pa0;
        *(uint4*)&As[arow1 * SSTR + acg1] = pa1;
        *(uint4*)&Bs[arow0 * SSTR + acg0] = pb0;
        *(uint4*)&Bs[arow1 * SSTR + acg1] = pb1;
        __syncthreads();
        // prefetch next tile while computing
        int kn = k0 + BK;
        if (kn < K) {
            int gm0 = bm + arow0, gm1 = bm + arow1;
            pa0 = (gm0 < M) ? *(const uint4*)&A[(size_t)gm0 * K + kn + acg0] : make_uint4(0,0,0,0);
            pa1 = (gm1 < M) ? *(const uint4*)&A[(size_t)gm1 * K + kn + acg1] : make_uint4(0,0,0,0);
            pb0 = *(const uint4*)&Bt[(size_t)(bn + arow0) * K + kn + acg0];
            pb1 = *(const uint4*)&Bt[(size_t)(bn + arow1) * K + kn + acg1];
        }
#pragma unroll
        for (int ks = 0; ks < 2; ks++) {
            const int kk = ks * 16;
            uint32_t a[2][4];
#pragma unroll
            for (int mt = 0; mt < 2; mt++) {
                int base = wm + mt * 16;
                a[mt][0] = *(const uint32_t*)&As[(base + r    ) * SSTR + kk + 2 * c];
                a[mt][1] = *(const uint32_t*)&As[(base + r + 8) * SSTR + kk + 2 * c];
                a[mt][2] = *(const uint32_t*)&As[(base + r    ) * SSTR + kk + 8 + 2 * c];
                a[mt][3] = *(const uint32_t*)&As[(base + r + 8) * SSTR + kk + 8 + 2 * c];
            }
#pragma unroll
            for (int nt = 0; nt < 8; nt++) {
                uint32_t b0 = *(const uint32_t*)&Bs[(wn + nt * 8 + r) * SSTR + kk + 2 * c];
                uint32_t b1 = *(const uint32_t*)&Bs[(wn + nt * 8 + r) * SSTR + kk + 8 + 2 * c];
#pragma unroll
                for (int mt = 0; mt < 2; mt++) {
                    asm volatile(
                        "mma.sync.aligned.m16n8k16.row.col.f32.f16.f16.f32 "
                        "{%0,%1,%2,%3}, {%4,%5,%6,%7}, {%8,%9}, {%0,%1,%2,%3};"
                        : "+f"(acc[mt][nt][0]), "+f"(acc[mt][nt][1]),
                          "+f"(acc[mt][nt][2]), "+f"(acc[mt][nt][3])
                        : "r"(a[mt][0]), "r"(a[mt][1]), "r"(a[mt][2]), "r"(a[mt][3]),
                          "r"(b0), "r"(b1));
                }
            }
        }
        __syncthreads();
    }
#pragma unroll
    for (int mt = 0; mt < 2; mt++) {
        int row0 = bm + wm + mt * 16 + r;
#pragma unroll
        for (int nt = 0; nt < 8; nt++) {
            int cc = bn + wn + nt * 8 + 2 * c;
            if (row0 < M)
                *(__half2*)&C[(size_t)row0 * HID + cc] =
                    __floats2half2_rn(acc[mt][nt][0], acc[mt][nt][1]);
            if (row0 + 8 < M)
                *(__half2*)&C[(size_t)(row0 + 8) * HID + cc] =
                    __floats2half2_rn(acc[mt][nt][2], acc[mt][nt][3]);
        }
    }
}

// ---------------- aggregate (atomic-free gather, fp16 features) --------------
template <bool POOL>
__global__ __launch_bounds__(256) void k_aggregate_h(const __half* __restrict__ xw,
                                                     const int* __restrict__ off,
                                                     const int2* __restrict__ edge,
                                                     const float* __restrict__ dis,
                                                     const float* __restrict__ bias,
                                                     __half* __restrict__ out,
                                                     const int* __restrict__ batch,
                                                     float* __restrict__ pooled) {
    int nid  = blockIdx.x * 8 + (threadIdx.x >> 5);
    int lane = threadIdx.x & 31;
    if (nid >= N_NODES) return;
    float d  = dis[nid];
    float d2 = d * d;
    float f[8], acc[8];
    uint4 sv = *(const uint4*)&xw[(size_t)nid * HID + lane * 8];
    h8f(sv, f);
    float4 b0 = *(const float4*)&bias[lane * 8];
    float4 b1 = *(const float4*)&bias[lane * 8 + 4];
    acc[0] = fmaf(f[0], d2, b0.x); acc[1] = fmaf(f[1], d2, b0.y);
    acc[2] = fmaf(f[2], d2, b0.z); acc[3] = fmaf(f[3], d2, b0.w);
    acc[4] = fmaf(f[4], d2, b1.x); acc[5] = fmaf(f[5], d2, b1.y);
    acc[6] = fmaf(f[6], d2, b1.z); acc[7] = fmaf(f[7], d2, b1.w);
    int s = off[nid], e = off[nid + 1];
    int j = s;
    for (; j + 1 < e; j += 2) {
        int2 e0 = __ldg(&edge[j]);
        int2 e1 = __ldg(&edge[j + 1]);
        float w0 = __int_as_float(e0.y), w1 = __int_as_float(e1.y);
        uint4 v0 = *(const uint4*)&xw[(size_t)e0.x * HID + lane * 8];
        uint4 v1 = *(const uint4*)&xw[(size_t)e1.x * HID + lane * 8];
        float g0[8], g1[8];
        h8f(v0, g0); h8f(v1, g1);
#pragma unroll
        for (int q = 0; q < 8; q++) acc[q] = fmaf(g0[q], w0, acc[q]);
#pragma unroll
        for (int q = 0; q < 8; q++) acc[q] = fmaf(g1[q], w1, acc[q]);
    }
    if (j < e) {
        int2 e0 = __ldg(&edge[j]);
        float w0 = __int_as_float(e0.y);
        uint4 v0 = *(const uint4*)&xw[(size_t)e0.x * HID + lane * 8];
        float g0[8];
        h8f(v0, g0);
#pragma unroll
        for (int q = 0; q < 8; q++) acc[q] = fmaf(g0[q], w0, acc[q]);
    }
#pragma unroll
    for (int q = 0; q < 8; q++) acc[q] = fmaxf(acc[q], 0.0f);
    if (POOL) {
        int bg = batch[nid];
        red_add_v4(&pooled[(size_t)bg * HID + lane * 8],
                   make_float4(acc[0], acc[1], acc[2], acc[3]));
        red_add_v4(&pooled[(size_t)bg * HID + lane * 8 + 4],
                   make_float4(acc[4], acc[5], acc[6], acc[7]));
    } else {
        uint4 o;
        *(__half2*)&o.x = __floats2half2_rn(acc[0], acc[1]);
        *(__half2*)&o.y = __floats2half2_rn(acc[2], acc[3]);
        *(__half2*)&o.z = __floats2half2_rn(acc[4], acc[5]);
        *(__half2*)&o.w = __floats2half2_rn(acc[6], acc[7]);
        *(uint4*)&out[(size_t)nid * HID + lane * 8] = o;
    }
}

// ---------------- FFN --------------------------------------------------------
__global__ __launch_bounds__(256) void k_ffn(const float* __restrict__ pooled,
                                             const float* __restrict__ counts,
                                             const float* __restrict__ Wf,
                                             const float* __restrict__ bf,
                                             const float* __restrict__ Wo,
                                             const float* __restrict__ bo,
                                             float* __restrict__ out) {
    int g = blockIdx.x;
    int t = threadIdx.x;
    __shared__ float prow[HID];
    __shared__ float red[HID];
    float inv = 1.0f / fmaxf(counts[g], 1.0f);
    prow[t] = pooled[g * HID + t] * inv;
    __syncthreads();
    float acc = bf[t];
#pragma unroll 8
    for (int k = 0; k < HID; k++) acc = fmaf(prow[k], Wf[k * HID + t], acc);
    red[t] = fmaxf(acc, 0.0f) * Wo[t];
    __syncthreads();
    for (int s = 128; s > 0; s >>= 1) {
        if (t < s) red[t] += red[t + s];
        __syncthreads();
    }
    if (t == 0) out[g] = red[0] + bo[0];
}

// ---------------- host side ---------------------------------------------------
extern "C" void kernel_launch(void* const* d_in, const int* in_sizes, int n_in,
                              void* d_out, int out_size) {
    const float* x    = (const float*)d_in[0];
    const int*   ei   = (const int*)d_in[1];
    const int*   batch= (const int*)d_in[2];
    const float* W1   = (const float*)d_in[3];
    const float* b1   = (const float*)d_in[4];
    const float* W2   = (const float*)d_in[5];
    const float* b2   = (const float*)d_in[6];
    const float* W3   = (const float*)d_in[7];
    const float* b3   = (const float*)d_in[8];
    const float* Wf   = (const float*)d_in[9];
    const float* bf   = (const float*)d_in[10];
    const float* Wo   = (const float*)d_in[11];
    const float* bo   = (const float*)d_in[12];
    float* out = (float*)d_out;

    const int* row = ei;
    const int* col = ei + N_EDGES;

    int *ideg, *off, *cursor, *bsum, *boff;
    int2* edge;
    float *dis, *pooled, *counts;
    __half *xh, *Wt, *xw, *hA, *hB;
    cudaGetSymbolAddress((void**)&ideg,   g_ideg);
    cudaGetSymbolAddress((void**)&off,    g_off);
    cudaGetSymbolAddress((void**)&cursor, g_cursor);
    cudaGetSymbolAddress((void**)&bsum,   g_bsum);
    cudaGetSymbolAddress((void**)&boff,   g_boff);
    cudaGetSymbolAddress((void**)&edge,   g_edge);
    cudaGetSymbolAddress((void**)&dis,    g_dis);
    cudaGetSymbolAddress((void**)&xh,     g_xh);
    cudaGetSymbolAddress((void**)&Wt,     g_Wt);
    cudaGetSymbolAddress((void**)&xw,     g_xw);
    cudaGetSymbolAddress((void**)&hA,     g_hA);
    cudaGetSymbolAddress((void**)&hB,     g_hB);
    cudaGetSymbolAddress((void**)&pooled, g_pooled);
    cudaGetSymbolAddress((void**)&counts, g_counts);

    __half* Wt1 = Wt;
    __half* Wt2 = Wt + IN_CH * HID;
    __half* Wt3 = Wt2 + HID * HID;

    // ---- CSR build + prep ----
    k_zero<<<(N_GRAPHS * HID + 255) / 256, 256>>>(ideg, pooled, counts);
    k_count<<<(N_EDGES + 255) / 256, 256>>>(col, ideg, batch, counts);
    k_scanA<<<NB, 256>>>(ideg, bsum);
    k_scanB<<<1, 1>>>(bsum, boff, off);
    k_scanC<<<NB, 1024>>>(ideg, boff, off, cursor, dis);
    k_fill<<<(N_EDGES + 255) / 256, 256>>>(row, col, dis, cursor, edge);
    int prep_items = XF4 + W1E + 2 * W23E;
    k_prep<<<(prep_items + 255) / 256, 256>>>(x, xh, W1, W2, W3, Wt);

    dim3 gemm_grid(HID / BN, (N_NODES + BM - 1) / BM);
    int node_blocks = (N_NODES + 7) / 8;

    // ---- layer 1 ----
    k_hgemm<<<gemm_grid, 256>>>(xh, Wt1, xw, N_NODES, IN_CH);
    k_aggregate_h<false><<<node_blocks, 256>>>(xw, off, edge, dis, b1, hA, batch, pooled);
    // ---- layer 2 ----
    k_hgemm<<<gemm_grid, 256>>>(hA, Wt2, xw, N_NODES, HID);
    k_aggregate_h<false><<<node_blocks, 256>>>(xw, off, edge, dis, b2, hB, batch, pooled);
    // ---- layer 3 (pool fused) ----
    k_hgemm<<<gemm_grid, 256>>>(hB, Wt3, xw, N_NODES, HID);
    k_aggregate_h<true><<<node_blocks, 256>>>(xw, off, edge, dis, b3, hA, batch, pooled);

    // ---- FFN ----
    k_ffn<<<N_GRAPHS, HID>>>(pooled, counts, Wf, bf, Wo, bo, out);
}

// round 6
// speedup vs baseline: 6.2130x; 1.0224x over previous
#include <cuda_runtime.h>
#include <cuda_fp16.h>
#include <cstdint>

#define N_NODES 50000
#define N_EDGES 800000
#define N_GRAPHS 256
#define IN_CH 128
#define HID 256
#define NB 49   // scan blocks of 1024

// ---------------- scratch (device globals; no allocation allowed) -------------
__device__ int   g_ideg[N_NODES];
__device__ int   g_off[N_NODES + 1];
__device__ int   g_cursor[N_NODES];
__device__ int   g_bsum[NB];
__device__ int   g_boff[NB];
__device__ __align__(16) int2 g_edge[N_EDGES];   // {src, w-as-int}
__device__ float g_dis[N_NODES];
__device__ __align__(16) __half g_xh[(size_t)N_NODES * IN_CH];
__device__ __align__(16) __half g_xagg[(size_t)N_NODES * IN_CH];
__device__ __align__(16) __half g_Wt[(IN_CH + HID + HID) * HID];
__device__ __align__(16) __half g_xw[(size_t)N_NODES * HID];
__device__ __align__(16) __half g_hA[(size_t)N_NODES * HID];
__device__ __align__(16) __half g_hB[(size_t)N_NODES * HID];
__device__ float g_pooled[N_GRAPHS * HID];
__device__ float g_counts[N_GRAPHS];

// ---------------- helpers ----------------------------------------------------
__device__ __forceinline__ void red_add_v4(float* addr, float4 v) {
    asm volatile("red.global.add.v4.f32 [%0], {%1,%2,%3,%4};"
                 :: "l"(addr), "f"(v.x), "f"(v.y), "f"(v.z), "f"(v.w)
                 : "memory");
}

__device__ __forceinline__ void h8f(uint4 v, float* f) {
    float2 p0 = __half22float2(*(const __half2*)&v.x);
    float2 p1 = __half22float2(*(const __half2*)&v.y);
    float2 p2 = __half22float2(*(const __half2*)&v.z);
    float2 p3 = __half22float2(*(const __half2*)&v.w);
    f[0] = p0.x; f[1] = p0.y; f[2] = p1.x; f[3] = p1.y;
    f[4] = p2.x; f[5] = p2.y; f[6] = p3.x; f[7] = p3.y;
}

typedef unsigned long long u64t;
__device__ __forceinline__ u64t packf2(float x, float y) {
    u64t u; asm("mov.b64 %0, {%1,%2};" : "=l"(u) : "f"(x), "f"(y)); return u;
}
__device__ __forceinline__ float2 unpackf2(u64t u) {
    float2 f; asm("mov.b64 {%0,%1}, %2;" : "=f"(f.x), "=f"(f.y) : "l"(u)); return f;
}
#define FMA_F32X2(d, a, b, c) \
    asm("fma.rn.f32x2 %0, %1, %2, %3;" : "=l"(d) : "l"(a), "l"(b), "l"(c))

// ---------------- fused prep: x->fp16, W1/W2/W3 -> transposed fp16 -----------
#define XF4   (N_NODES * IN_CH / 4)
#define W1E   (IN_CH * HID)
#define W23E  (HID * HID)
__global__ void k_prep(const float* __restrict__ x, __half* __restrict__ xh,
                       const float* __restrict__ W1, const float* __restrict__ W2,
                       const float* __restrict__ W3, __half* __restrict__ Wt) {
    int i = blockIdx.x * blockDim.x + threadIdx.x;
    if (i < XF4) {
        float4 v = ((const float4*)x)[i];
        ((__half2*)xh)[i * 2]     = __floats2half2_rn(v.x, v.y);
        ((__half2*)xh)[i * 2 + 1] = __floats2half2_rn(v.z, v.w);
        return;
    }
    i -= XF4;
    if (i < W1E) {
        int k = i >> 8, n = i & 255;
        Wt[(size_t)n * IN_CH + k] = __float2half(W1[i]);
        return;
    }
    i -= W1E;
    if (i < W23E) {
        int k = i >> 8, n = i & 255;
        Wt[W1E + (size_t)n * HID + k] = __float2half(W2[i]);
        return;
    }
    i -= W23E;
    if (i < W23E) {
        int k = i >> 8, n = i & 255;
        Wt[W1E + W23E + (size_t)n * HID + k] = __float2half(W3[i]);
    }
}

// ---------------- CSR build ---------------------------------------------------
__global__ void k_zero(int* ideg, float* pooled, float* counts) {
    int i = blockIdx.x * blockDim.x + threadIdx.x;
    if (i < N_NODES) ideg[i] = 0;
    if (i < N_GRAPHS * HID) pooled[i] = 0.0f;
    if (i < N_GRAPHS) counts[i] = 0.0f;
}

__global__ void k_count(const int* __restrict__ col, int* __restrict__ ideg,
                        const int* __restrict__ batch, float* __restrict__ counts) {
    int e = blockIdx.x * blockDim.x + threadIdx.x;
    if (e < N_EDGES) atomicAdd(&ideg[col[e]], 1);
    if (e < N_NODES) atomicAdd(&counts[batch[e]], 1.0f);
}

__global__ __launch_bounds__(256) void k_scanA(const int* __restrict__ ideg,
                                               int* __restrict__ bsum) {
    __shared__ int ws[8];
    int b = blockIdx.x, t = threadIdx.x;
    int base = b * 1024 + t * 4;
    int s = 0;
#pragma unroll
    for (int q = 0; q < 4; q++) {
        int i = base + q;
        if (i < N_NODES) s += ideg[i];
    }
#pragma unroll
    for (int o = 16; o; o >>= 1) s += __shfl_down_sync(0xffffffffu, s, o);
    if ((t & 31) == 0) ws[t >> 5] = s;
    __syncthreads();
    if (t < 8) {
        int v = ws[t];
#pragma unroll
        for (int o = 4; o; o >>= 1) v += __shfl_down_sync(0xffu, v, o);
        if (t == 0) bsum[b] = v;
    }
}

// warp-parallel scan of NB block sums (2 elems per lane)
__global__ void k_scanB(const int* __restrict__ bsum, int* __restrict__ boff,
                        int* __restrict__ off) {
    int lane = threadIdx.x;
    int v0 = (lane < NB) ? bsum[lane] : 0;
    int v1 = (lane + 32 < NB) ? bsum[lane + 32] : 0;
    int p0 = v0, p1 = v1;
#pragma unroll
    for (int s = 1; s < 32; s <<= 1) {
        int u0 = __shfl_up_sync(0xffffffffu, p0, s);
        int u1 = __shfl_up_sync(0xffffffffu, p1, s);
        if (lane >= s) { p0 += u0; p1 += u1; }
    }
    int tot0 = __shfl_sync(0xffffffffu, p0, 31);
    if (lane < NB) boff[lane] = p0 - v0;
    if (lane + 32 < NB) boff[lane + 32] = tot0 + p1 - v1;
    if (lane == 31) off[N_NODES] = tot0 + p1;
}

__global__ __launch_bounds__(1024) void k_scanC(const int* __restrict__ ideg,
                                                const int* __restrict__ boff,
                                                int* __restrict__ off,
                                                int* __restrict__ cursor,
                                                float* __restrict__ dis) {
    __shared__ int warpsum[32];
    int t = threadIdx.x;
    int lane = t & 31, w = t >> 5;
    int i = blockIdx.x * 1024 + t;
    int v = (i < N_NODES) ? ideg[i] : 0;
    int inc = v;
#pragma unroll
    for (int s = 1; s < 32; s <<= 1) {
        int u = __shfl_up_sync(0xffffffffu, inc, s);
        if (lane >= s) inc += u;
    }
    if (lane == 31) warpsum[w] = inc;
    __syncthreads();
    if (w == 0) {
        int wi = warpsum[lane];
#pragma unroll
        for (int s = 1; s < 32; s <<= 1) {
            int u = __shfl_up_sync(0xffffffffu, wi, s);
            if (lane >= s) wi += u;
        }
        warpsum[lane] = wi;
    }
    __syncthreads();
    int woff = (w > 0) ? warpsum[w - 1] : 0;
    if (i < N_NODES) {
        int e = boff[blockIdx.x] + woff + inc - v;
        off[i] = e;
        cursor[i] = e;
        dis[i] = rsqrtf((float)(v + 1));
    }
}

__global__ void k_fill(const int* __restrict__ row, const int* __restrict__ col,
                       const float* __restrict__ dis,
                       int* __restrict__ cursor, int2* __restrict__ edge) {
    int e = blockIdx.x * blockDim.x + threadIdx.x;
    if (e >= N_EDGES) return;
    int r = row[e], c = col[e];
    int pos = atomicAdd(&cursor[c], 1);
    edge[pos] = make_int2(r, __float_as_int(dis[r] * dis[c]));
}

// ---------------- layer-0 pre-aggregate: xagg = Â x  (128 ch, fp32 f32x2) ----
__global__ __launch_bounds__(256) void k_agg0(const __half* __restrict__ xh,
                                              const int* __restrict__ off,
                                              const int2* __restrict__ edge,
                                              const float* __restrict__ dis,
                                              __half* __restrict__ xagg) {
    int nid  = blockIdx.x * 8 + (threadIdx.x >> 5);
    int lane = threadIdx.x & 31;
    if (nid >= N_NODES) return;
    float d  = dis[nid];
    float d2 = d * d;
    uint2 sv = *(const uint2*)&xh[(size_t)nid * IN_CH + lane * 4];
    float2 s0 = __half22float2(*(const __half2*)&sv.x);
    float2 s1 = __half22float2(*(const __half2*)&sv.y);
    u64t a0 = packf2(s0.x * d2, s0.y * d2);
    u64t a1 = packf2(s1.x * d2, s1.y * d2);
    int s = off[nid], e = off[nid + 1];
    int j = s;
    for (; j + 1 < e; j += 2) {
        int2 e0 = __ldg(&edge[j]);
        int2 e1 = __ldg(&edge[j + 1]);
        float w0 = __int_as_float(e0.y), w1 = __int_as_float(e1.y);
        u64t wd0 = packf2(w0, w0), wd1 = packf2(w1, w1);
        uint2 v0 = *(const uint2*)&xh[(size_t)e0.x * IN_CH + lane * 4];
        uint2 v1 = *(const uint2*)&xh[(size_t)e1.x * IN_CH + lane * 4];
        float2 f00 = __half22float2(*(const __half2*)&v0.x);
        float2 f01 = __half22float2(*(const __half2*)&v0.y);
        float2 f10 = __half22float2(*(const __half2*)&v1.x);
        float2 f11 = __half22float2(*(const __half2*)&v1.y);
        FMA_F32X2(a0, packf2(f00.x, f00.y), wd0, a0);
        FMA_F32X2(a1, packf2(f01.x, f01.y), wd0, a1);
        FMA_F32X2(a0, packf2(f10.x, f10.y), wd1, a0);
        FMA_F32X2(a1, packf2(f11.x, f11.y), wd1, a1);
    }
    if (j < e) {
        int2 e0 = __ldg(&edge[j]);
        float w0 = __int_as_float(e0.y);
        u64t wd0 = packf2(w0, w0);
        uint2 v0 = *(const uint2*)&xh[(size_t)e0.x * IN_CH + lane * 4];
        float2 f00 = __half22float2(*(const __half2*)&v0.x);
        float2 f01 = __half22float2(*(const __half2*)&v0.y);
        FMA_F32X2(a0, packf2(f00.x, f00.y), wd0, a0);
        FMA_F32X2(a1, packf2(f01.x, f01.y), wd0, a1);
    }
    float2 r0 = unpackf2(a0), r1 = unpackf2(a1);
    uint2 o;
    *(__half2*)&o.x = __floats2half2_rn(r0.x, r0.y);
    *(__half2*)&o.y = __floats2half2_rn(r1.x, r1.y);
    *(uint2*)&xagg[(size_t)nid * IN_CH + lane * 4] = o;
}

// ---------------- FP16 tensor-core GEMM with register-prefetch pipeline ------
// BIASRELU: epilogue applies out = relu(acc + bias[col]).
#define BM 128
#define BN 128
#define BK 32
#define SSTR 72

template <bool BIASRELU>
__global__ __launch_bounds__(256) void k_hgemm(const __half* __restrict__ A,
                                               const __half* __restrict__ Bt,
                                               __half* __restrict__ C,
                                               const float* __restrict__ bias,
                                               int M, int K) {
    __shared__ __half As[BM * SSTR];
    __shared__ __half Bs[BN * SSTR];
    const int tid  = threadIdx.x;
    const int warp = tid >> 5, lane = tid & 31;
    const int wm = (warp & 3) * 32;
    const int wn = (warp >> 2) * 64;
    const int r = lane >> 2, c = lane & 3;
    const int bm = blockIdx.y * BM;
    const int bn = blockIdx.x * BN;

    const int arow0 = (tid) >> 2,        acg0 = ((tid) & 3) * 8;
    const int arow1 = (tid + 256) >> 2,  acg1 = ((tid + 256) & 3) * 8;

    float acc[2][8][4];
#pragma unroll
    for (int mt = 0; mt < 2; mt++)
#pragma unroll
        for (int nt = 0; nt < 8; nt++)
#pragma unroll
            for (int q = 0; q < 4; q++) acc[mt][nt][q] = 0.0f;

    uint4 pa0, pa1, pb0, pb1;
    {
        int gm0 = bm + arow0, gm1 = bm + arow1;
        pa0 = (gm0 < M) ? *(const uint4*)&A[(size_t)gm0 * K + acg0] : make_uint4(0,0,0,0);
        pa1 = (gm1 < M) ? *(const uint4*)&A[(size_t)gm1 * K + acg1] : make_uint4(0,0,0,0);
        pb0 = *(const uint4*)&Bt[(size_t)(bn + arow0) * K + acg0];
        pb1 = *(const uint4*)&Bt[(size_t)(bn + arow1) * K + acg1];
    }

    for (int k0 = 0; k0 < K; k0 += BK) {
        *(uint4*)&As[arow0 * SSTR + acg0] = pa0;
        *(uint4*)&As[arow1 * SSTR + acg1] = pa1;
        *(uint4*)&Bs[arow0 * SSTR + acg0] = pb0;
        *(uint4*)&Bs[arow1 * SSTR + acg1] = pb1;
        __syncthreads();
        int kn = k0 + BK;
        if (kn < K) {
            int gm0 = bm + arow0, gm1 = bm + arow1;
            pa0 = (gm0 < M) ? *(const uint4*)&A[(size_t)gm0 * K + kn + acg0] : make_uint4(0,0,0,0);
            pa1 = (gm1 < M) ? *(const uint4*)&A[(size_t)gm1 * K + kn + acg1] : make_uint4(0,0,0,0);
            pb0 = *(const uint4*)&Bt[(size_t)(bn + arow0) * K + kn + acg0];
            pb1 = *(const uint4*)&Bt[(size_t)(bn + arow1) * K + kn + acg1];
        }
#pragma unroll
        for (int ks = 0; ks < 2; ks++) {
            const int kk = ks * 16;
            uint32_t a[2][4];
#pragma unroll
            for (int mt = 0; mt < 2; mt++) {
                int base = wm + mt * 16;
                a[mt][0] = *(const uint32_t*)&As[(base + r    ) * SSTR + kk + 2 * c];
                a[mt][1] = *(const uint32_t*)&As[(base + r + 8) * SSTR + kk + 2 * c];
                a[mt][2] = *(const uint32_t*)&As[(base + r    ) * SSTR + kk + 8 + 2 * c];
                a[mt][3] = *(const uint32_t*)&As[(base + r + 8) * SSTR + kk + 8 + 2 * c];
            }
#pragma unroll
            for (int nt = 0; nt < 8; nt++) {
                uint32_t b0 = *(const uint32_t*)&Bs[(wn + nt * 8 + r) * SSTR + kk + 2 * c];
                uint32_t b1 = *(const uint32_t*)&Bs[(wn + nt * 8 + r) * SSTR + kk + 8 + 2 * c];
#pragma unroll
                for (int mt = 0; mt < 2; mt++) {
                    asm volatile(
                        "mma.sync.aligned.m16n8k16.row.col.f32.f16.f16.f32 "
                        "{%0,%1,%2,%3}, {%4,%5,%6,%7}, {%8,%9}, {%0,%1,%2,%3};"
                        : "+f"(acc[mt][nt][0]), "+f"(acc[mt][nt][1]),
                          "+f"(acc[mt][nt][2]), "+f"(acc[mt][nt][3])
                        : "r"(a[mt][0]), "r"(a[mt][1]), "r"(a[mt][2]), "r"(a[mt][3]),
                          "r"(b0), "r"(b1));
                }
            }
        }
        __syncthreads();
    }
#pragma unroll
    for (int mt = 0; mt < 2; mt++) {
        int row0 = bm + wm + mt * 16 + r;
#pragma unroll
        for (int nt = 0; nt < 8; nt++) {
            int cc = bn + wn + nt * 8 + 2 * c;
            float v0 = acc[mt][nt][0], v1 = acc[mt][nt][1];
            float v2 = acc[mt][nt][2], v3 = acc[mt][nt][3];
            if (BIASRELU) {
                float2 bv = *(const float2*)&bias[cc];
                v0 = fmaxf(v0 + bv.x, 0.f); v1 = fmaxf(v1 + bv.y, 0.f);
                v2 = fmaxf(v2 + bv.x, 0.f); v3 = fmaxf(v3 + bv.y, 0.f);
            }
            if (row0 < M)
                *(__half2*)&C[(size_t)row0 * HID + cc] = __floats2half2_rn(v0, v1);
            if (row0 + 8 < M)
                *(__half2*)&C[(size_t)(row0 + 8) * HID + cc] = __floats2half2_rn(v2, v3);
        }
    }
}

// ---------------- full aggregate (256 ch, dual-chain HFMA2 accumulation) -----
template <bool POOL>
__global__ __launch_bounds__(256) void k_agg_h(const __half* __restrict__ xw,
                                               const int* __restrict__ off,
                                               const int2* __restrict__ edge,
                                               const float* __restrict__ dis,
                                               const float* __restrict__ bias,
                                               __half* __restrict__ out,
                                               const int* __restrict__ batch,
                                               float* __restrict__ pooled) {
    int nid  = blockIdx.x * 8 + (threadIdx.x >> 5);
    int lane = threadIdx.x & 31;
    if (nid >= N_NODES) return;
    __half2 c0[4], c1[4];
    const __half2 hz = __float2half2_rn(0.0f);
#pragma unroll
    for (int q = 0; q < 4; q++) { c0[q] = hz; c1[q] = hz; }
    int s = off[nid], e = off[nid + 1];
    int j = s;
    for (; j + 1 < e; j += 2) {
        int2 e0 = __ldg(&edge[j]);
        int2 e1 = __ldg(&edge[j + 1]);
        __half2 w0 = __float2half2_rn(__int_as_float(e0.y));
        __half2 w1 = __float2half2_rn(__int_as_float(e1.y));
        uint4 v0 = *(const uint4*)&xw[(size_t)e0.x * HID + lane * 8];
        uint4 v1 = *(const uint4*)&xw[(size_t)e1.x * HID + lane * 8];
        c0[0] = __hfma2(*(const __half2*)&v0.x, w0, c0[0]);
        c0[1] = __hfma2(*(const __half2*)&v0.y, w0, c0[1]);
        c0[2] = __hfma2(*(const __half2*)&v0.z, w0, c0[2]);
        c0[3] = __hfma2(*(const __half2*)&v0.w, w0, c0[3]);
        c1[0] = __hfma2(*(const __half2*)&v1.x, w1, c1[0]);
        c1[1] = __hfma2(*(const __half2*)&v1.y, w1, c1[1]);
        c1[2] = __hfma2(*(const __half2*)&v1.z, w1, c1[2]);
        c1[3] = __hfma2(*(const __half2*)&v1.w, w1, c1[3]);
    }
    if (j < e) {
        int2 e0 = __ldg(&edge[j]);
        __half2 w0 = __float2half2_rn(__int_as_float(e0.y));
        uint4 v0 = *(const uint4*)&xw[(size_t)e0.x * HID + lane * 8];
        c0[0] = __hfma2(*(const __half2*)&v0.x, w0, c0[0]);
        c0[1] = __hfma2(*(const __half2*)&v0.y, w0, c0[1]);
        c0[2] = __hfma2(*(const __half2*)&v0.z, w0, c0[2]);
        c0[3] = __hfma2(*(const __half2*)&v0.w, w0, c0[3]);
    }
    // combine chains in fp32 + self-loop + bias + relu
    float d = dis[nid];
    float d2 = d * d;
    float f[8], acc[8];
    uint4 sv = *(const uint4*)&xw[(size_t)nid * HID + lane * 8];
    h8f(sv, f);
#pragma unroll
    for (int q = 0; q < 4; q++) {
        float2 fa = __half22float2(c0[q]);
        float2 fb = __half22float2(c1[q]);
        acc[2 * q]     = fa.x + fb.x;
        acc[2 * q + 1] = fa.y + fb.y;
    }
    float4 b0 = *(const float4*)&bias[lane * 8];
    float4 b1 = *(const float4*)&bias[lane * 8 + 4];
    acc[0] = fmaf(f[0], d2, acc[0]) + b0.x; acc[1] = fmaf(f[1], d2, acc[1]) + b0.y;
    acc[2] = fmaf(f[2], d2, acc[2]) + b0.z; acc[3] = fmaf(f[3], d2, acc[3]) + b0.w;
    acc[4] = fmaf(f[4], d2, acc[4]) + b1.x; acc[5] = fmaf(f[5], d2, acc[5]) + b1.y;
    acc[6] = fmaf(f[6], d2, acc[6]) + b1.z; acc[7] = fmaf(f[7], d2, acc[7]) + b1.w;
#pragma unroll
    for (int q = 0; q < 8; q++) acc[q] = fmaxf(acc[q], 0.0f);
    if (POOL) {
        int bg = batch[nid];
        red_add_v4(&pooled[(size_t)bg * HID + lane * 8],
                   make_float4(acc[0], acc[1], acc[2], acc[3]));
        red_add_v4(&pooled[(size_t)bg * HID + lane * 8 + 4],
                   make_float4(acc[4], acc[5], acc[6], acc[7]));
    } else {
        uint4 o;
        *(__half2*)&o.x = __floats2half2_rn(acc[0], acc[1]);
        *(__half2*)&o.y = __floats2half2_rn(acc[2], acc[3]);
        *(__half2*)&o.z = __floats2half2_rn(acc[4], acc[5]);
        *(__half2*)&o.w = __floats2half2_rn(acc[6], acc[7]);
        *(uint4*)&out[(size_t)nid * HID + lane * 8] = o;
    }
}

// ---------------- FFN --------------------------------------------------------
__global__ __launch_bounds__(256) void k_ffn(const float* __restrict__ pooled,
                                             const float* __restrict__ counts,
                                             const float* __restrict__ Wf,
                                             const float* __restrict__ bf,
                                             const float* __restrict__ Wo,
                                             const float* __restrict__ bo,
                                             float* __restrict__ out) {
    int g = blockIdx.x;
    int t = threadIdx.x;
    __shared__ float prow[HID];
    __shared__ float red[HID];
    float inv = 1.0f / fmaxf(counts[g], 1.0f);
    prow[t] = pooled[g * HID + t] * inv;
    __syncthreads();
    float acc = bf[t];
#pragma unroll 8
    for (int k = 0; k < HID; k++) acc = fmaf(prow[k], Wf[k * HID + t], acc);
    red[t] = fmaxf(acc, 0.0f) * Wo[t];
    __syncthreads();
    for (int s = 128; s > 0; s >>= 1) {
        if (t < s) red[t] += red[t + s];
        __syncthreads();
    }
    if (t == 0) out[g] = red[0] + bo[0];
}

// ---------------- host side ---------------------------------------------------
extern "C" void kernel_launch(void* const* d_in, const int* in_sizes, int n_in,
                              void* d_out, int out_size) {
    const float* x    = (const float*)d_in[0];
    const int*   ei   = (const int*)d_in[1];
    const int*   batch= (const int*)d_in[2];
    const float* W1   = (const float*)d_in[3];
    const float* b1   = (const float*)d_in[4];
    const float* W2   = (const float*)d_in[5];
    const float* b2   = (const float*)d_in[6];
    const float* W3   = (const float*)d_in[7];
    const float* b3   = (const float*)d_in[8];
    const float* Wf   = (const float*)d_in[9];
    const float* bf   = (const float*)d_in[10];
    const float* Wo   = (const float*)d_in[11];
    const float* bo   = (const float*)d_in[12];
    float* out = (float*)d_out;

    const int* row = ei;
    const int* col = ei + N_EDGES;

    int *ideg, *off, *cursor, *bsum, *boff;
    int2* edge;
    float *dis, *pooled, *counts;
    __half *xh, *xagg, *Wt, *xw, *hA, *hB;
    cudaGetSymbolAddress((void**)&ideg,   g_ideg);
    cudaGetSymbolAddress((void**)&off,    g_off);
    cudaGetSymbolAddress((void**)&cursor, g_cursor);
    cudaGetSymbolAddress((void**)&bsum,   g_bsum);
    cudaGetSymbolAddress((void**)&boff,   g_boff);
    cudaGetSymbolAddress((void**)&edge,   g_edge);
    cudaGetSymbolAddress((void**)&dis,    g_dis);
    cudaGetSymbolAddress((void**)&xh,     g_xh);
    cudaGetSymbolAddress((void**)&xagg,   g_xagg);
    cudaGetSymbolAddress((void**)&Wt,     g_Wt);
    cudaGetSymbolAddress((void**)&xw,     g_xw);
    cudaGetSymbolAddress((void**)&hA,     g_hA);
    cudaGetSymbolAddress((void**)&hB,     g_hB);
    cudaGetSymbolAddress((void**)&pooled, g_pooled);
    cudaGetSymbolAddress((void**)&counts, g_counts);

    __half* Wt1 = Wt;
    __half* Wt2 = Wt + IN_CH * HID;
    __half* Wt3 = Wt2 + HID * HID;

    // ---- CSR build + prep ----
    k_zero<<<(N_GRAPHS * HID + 255) / 256, 256>>>(ideg, pooled, counts);
    k_count<<<(N_EDGES + 255) / 256, 256>>>(col, ideg, batch, counts);
    k_scanA<<<NB, 256>>>(ideg, bsum);
    k_scanB<<<1, 32>>>(bsum, boff, off);
    k_scanC<<<NB, 1024>>>(ideg, boff, off, cursor, dis);
    k_fill<<<(N_EDGES + 255) / 256, 256>>>(row, col, dis, cursor, edge);
    int prep_items = XF4 + W1E + 2 * W23E;
    k_prep<<<(prep_items + 255) / 256, 256>>>(x, xh, W1, W2, W3, Wt);

    dim3 gemm_grid(HID / BN, (N_NODES + BM - 1) / BM);
    int node_blocks = (N_NODES + 7) / 8;

    // ---- layer 1: pre-aggregate (128 ch) then GEMM with bias+relu ----
    k_agg0<<<node_blocks, 256>>>(xh, off, edge, dis, xagg);
    k_hgemm<true><<<gemm_grid, 256>>>(xagg, Wt1, hA, b1, N_NODES, IN_CH);
    // ---- layer 2 ----
    k_hgemm<false><<<gemm_grid, 256>>>(hA, Wt2, xw, nullptr, N_NODES, HID);
    k_agg_h<false><<<node_blocks, 256>>>(xw, off, edge, dis, b2, hB, batch, pooled);
    // ---- layer 3 (pool fused) ----
    k_hgemm<false><<<gemm_grid, 256>>>(hB, Wt3, xw, nullptr, N_NODES, HID);
    k_agg_h<true><<<node_blocks, 256>>>(xw, off, edge, dis, b3, nullptr, batch, pooled);

    // ---- FFN ----
    k_ffn<<<N_GRAPHS, HID>>>(pooled, counts, Wf, bf, Wo, bo, out);
}